// round 2
// baseline (speedup 1.0000x reference)
#include <cuda_runtime.h>
#include <cuda_bf16.h>
#include <math.h>

// ---------------- problem constants ----------------
#define TT   2048
#define HID  1024
#define NH   16
#define DK   64
#define DV   128
#define VAL  2048   // NH*DV
#define CONV 4

// ---------------- scratch (__device__ globals; no allocation allowed) ----------------
__device__ float g_xn  [TT * HID];   // rmsnorm(x)
__device__ float g_qpre[TT * HID];
__device__ float g_kpre[TT * HID];
__device__ float g_vpre[TT * VAL];
__device__ float g_gate[TT * VAL];
__device__ float g_q   [TT * HID];
__device__ float g_k   [TT * HID];
__device__ float g_v   [TT * VAL];
__device__ float g_araw[TT * NH];
__device__ float g_braw[TT * NH];
__device__ float g_beta[TT * NH];
__device__ float g_eg  [TT * NH];
__device__ float g_o   [TT * VAL];
__device__ float g_og  [TT * VAL];
__device__ float g_t1  [TT * HID];

// ---------------- RMSNorm ----------------
__global__ void rmsnorm_kernel(const float* __restrict__ x, const float* __restrict__ w,
                               float* __restrict__ y) {
    int row = blockIdx.x;
    int tid = threadIdx.x;                 // 256
    const float* xr = x + (size_t)row * HID;
    float v[4];
    float s = 0.f;
#pragma unroll
    for (int i = 0; i < 4; i++) { v[i] = xr[tid + i * 256]; s += v[i] * v[i]; }
    __shared__ float red[256];
    red[tid] = s; __syncthreads();
    for (int o = 128; o > 0; o >>= 1) { if (tid < o) red[tid] += red[tid + o]; __syncthreads(); }
    float scale = rsqrtf(red[0] * (1.f / HID) + 1e-6f);
#pragma unroll
    for (int i = 0; i < 4; i++)
        y[(size_t)row * HID + tid + i * 256] = v[i] * scale * w[tid + i * 256];
}

// ---------------- tiled SGEMM:  C[M,N] = A[M,K] @ W[N,K]^T  (all row-major) ----------------
#define BM 128
#define BN 128
#define BKD 16
__global__ __launch_bounds__(256) void sgemm_nt(const float* __restrict__ A,
                                                const float* __restrict__ W,
                                                float* __restrict__ C,
                                                int M, int N, int K) {
    __shared__ float As[BKD][BM];
    __shared__ float Ws[BKD][BN];
    int bm = blockIdx.y * BM;
    int bn = blockIdx.x * BN;
    int tid = threadIdx.x;
    int tx = tid % 16, ty = tid / 16;
    float acc[8][8];
#pragma unroll
    for (int i = 0; i < 8; i++)
#pragma unroll
        for (int j = 0; j < 8; j++) acc[i][j] = 0.f;

    int lr = tid >> 2;          // 0..63
    int lc = (tid & 3) * 4;     // 0,4,8,12

    for (int k0 = 0; k0 < K; k0 += BKD) {
#pragma unroll
        for (int p = 0; p < 2; p++) {
            int r = lr + p * 64;
            float4 av = *(const float4*)(A + (size_t)(bm + r) * K + k0 + lc);
            As[lc + 0][r] = av.x; As[lc + 1][r] = av.y; As[lc + 2][r] = av.z; As[lc + 3][r] = av.w;
            float4 wv = *(const float4*)(W + (size_t)(bn + r) * K + k0 + lc);
            Ws[lc + 0][r] = wv.x; Ws[lc + 1][r] = wv.y; Ws[lc + 2][r] = wv.z; Ws[lc + 3][r] = wv.w;
        }
        __syncthreads();
#pragma unroll
        for (int kk = 0; kk < BKD; kk++) {
            float a[8], b[8];
#pragma unroll
            for (int i = 0; i < 8; i++) a[i] = As[kk][ty * 8 + i];
#pragma unroll
            for (int j = 0; j < 8; j++) b[j] = Ws[kk][tx * 8 + j];
#pragma unroll
            for (int i = 0; i < 8; i++)
#pragma unroll
                for (int j = 0; j < 8; j++)
                    acc[i][j] += a[i] * b[j];
        }
        __syncthreads();
    }
#pragma unroll
    for (int i = 0; i < 8; i++)
#pragma unroll
        for (int j = 0; j < 8; j++)
            C[(size_t)(bm + ty * 8 + i) * N + bn + tx * 8 + j] = acc[i][j];
}

// ---------------- thin projection: R[T,16] = X[T,HID] @ W[16,HID]^T ----------------
__global__ void proj16_kernel(const float* __restrict__ X, const float* __restrict__ W,
                              float* __restrict__ R) {
    int gw = (blockIdx.x * blockDim.x + threadIdx.x) >> 5;
    int lane = threadIdx.x & 31;
    if (gw >= TT * NH) return;
    int m = gw >> 4, n = gw & 15;
    const float4* xr = (const float4*)(X + (size_t)m * HID);
    const float4* wr = (const float4*)(W + (size_t)n * HID);
    float s = 0.f;
#pragma unroll
    for (int i = 0; i < 8; i++) {
        float4 a = xr[lane + i * 32], b = wr[lane + i * 32];
        s += a.x * b.x + a.y * b.y + a.z * b.z + a.w * b.w;
    }
    for (int o = 16; o > 0; o >>= 1) s += __shfl_xor_sync(~0u, s, o);
    if (lane == 0) R[m * NH + n] = s;
}

// ---------------- beta = sigmoid(b), eg = exp(-exp(A_log)*softplus(a+dt_bias)) ----------------
__global__ void gate_scalar_kernel(const float* __restrict__ araw, const float* __restrict__ braw,
                                   const float* __restrict__ dt_bias, const float* __restrict__ A_log,
                                   float* __restrict__ beta, float* __restrict__ eg) {
    int i = blockIdx.x * blockDim.x + threadIdx.x;
    if (i >= TT * NH) return;
    int h = i & (NH - 1);
    beta[i] = 1.f / (1.f + expf(-braw[i]));
    float xv = araw[i] + dt_bias[h];
    float sp = (xv > 20.f) ? xv : log1pf(expf(xv));
    eg[i] = expf(-expf(A_log[h]) * sp);
}

// ---------------- causal depthwise conv(K=4)+silu then per-head postproc for q/k ----------------
__global__ void conv_qk_kernel(const float* __restrict__ pre, const float* __restrict__ cw,
                               float* __restrict__ out, int kmode) {
    // warp per (t,h); 128 threads -> 4 warps per block
    int gw = blockIdx.x * 4 + (threadIdx.x >> 5);
    int lane = threadIdx.x & 31;
    int t = gw >> 4, h = gw & 15;
    float y[2];
#pragma unroll
    for (int e = 0; e < 2; e++) {
        int d = lane + e * 32;
        int c = h * DK + d;
        float acc = 0.f;
#pragma unroll
        for (int i = 0; i < CONV; i++) {
            int tt = t - (CONV - 1) + i;
            float xv = (tt >= 0) ? pre[(size_t)tt * HID + c] : 0.f;
            acc += xv * cw[c * CONV + i];
        }
        y[e] = acc / (1.f + expf(-acc));   // silu
    }
    if (kmode) {                           // DC removal: subtract per-head mean
        float m = y[0] + y[1];
        for (int o = 16; o > 0; o >>= 1) m += __shfl_xor_sync(~0u, m, o);
        m *= (1.f / DK);
        y[0] -= m; y[1] -= m;
    }
    float ss = y[0] * y[0] + y[1] * y[1];
    for (int o = 16; o > 0; o >>= 1) ss += __shfl_xor_sync(~0u, ss, o);
    float sc = rsqrtf(ss + 1e-6f);
    if (!kmode) sc *= 0.125f;              // DK^-0.5
#pragma unroll
    for (int e = 0; e < 2; e++) {
        int d = lane + e * 32;
        out[(size_t)t * HID + h * DK + d] = y[e] * sc;
    }
}

// ---------------- causal depthwise conv(K=4)+silu for v ----------------
__global__ void conv_v_kernel(const float* __restrict__ pre, const float* __restrict__ cw,
                              float* __restrict__ out) {
    int i = blockIdx.x * blockDim.x + threadIdx.x;
    if (i >= TT * VAL) return;
    int t = i >> 11, c = i & (VAL - 1);
    float acc = 0.f;
#pragma unroll
    for (int j = 0; j < CONV; j++) {
        int tt = t - (CONV - 1) + j;
        float xv = (tt >= 0) ? pre[(size_t)tt * VAL + c] : 0.f;
        acc += xv * cw[c * CONV + j];
    }
    out[i] = acc / (1.f + expf(-acc));
}

// ---------------- gated delta-rule scan ----------------
// Columns of S[:,v] are independent. grid = 32 blocks (16 heads x 2 column halves),
// block = 128 threads (4 warps). 2 lanes per column (dk split 0:32 / 32:64),
// reductions via shfl_xor(16). k/q preloaded in 64-step chunks into shared.
__global__ __launch_bounds__(128) void scan_kernel(const float* __restrict__ q,
                                                   const float* __restrict__ k,
                                                   const float* __restrict__ v,
                                                   const float* __restrict__ beta,
                                                   const float* __restrict__ eg,
                                                   float* __restrict__ o) {
    const int h = blockIdx.x >> 1;
    const int colbase = (blockIdx.x & 1) * 64;
    const int tid = threadIdx.x;
    const int warp = tid >> 5, lane = tid & 31;
    const int col = colbase + warp * 16 + (lane & 15);
    const int half = lane >> 4;
    __shared__ float sk[64][64];
    __shared__ float sq[64][64];
    __shared__ float sb[64], se[64];
    float s[32];
#pragma unroll
    for (int i = 0; i < 32; i++) s[i] = 0.f;

    for (int c0 = 0; c0 < TT; c0 += 64) {
        __syncthreads();
#pragma unroll
        for (int i = 0; i < 8; i++) {
            int idx = tid + i * 128;           // 0..1023 (float4 index)
            int tl = idx >> 4, f4 = idx & 15;
            float4 kk = *(const float4*)(k + (size_t)(c0 + tl) * HID + h * DK + f4 * 4);
            *(float4*)&sk[tl][f4 * 4] = kk;
            float4 qq = *(const float4*)(q + (size_t)(c0 + tl) * HID + h * DK + f4 * 4);
            *(float4*)&sq[tl][f4 * 4] = qq;
        }
        if (tid < 64) {
            sb[tid] = beta[(size_t)(c0 + tid) * NH + h];
            se[tid] = eg[(size_t)(c0 + tid) * NH + h];
        }
        __syncthreads();
        for (int tl = 0; tl < 64; tl++) {
            int t = c0 + tl;
            float egv = se[tl], bt = sb[tl];
            float vt = v[(size_t)t * VAL + h * DV + col];
            float kr[32];
            float kv = 0.f;
#pragma unroll
            for (int j = 0; j < 8; j++) {
                float4 kk = *(const float4*)&sk[tl][half * 32 + j * 4];
                kr[j * 4 + 0] = kk.x; kr[j * 4 + 1] = kk.y;
                kr[j * 4 + 2] = kk.z; kr[j * 4 + 3] = kk.w;
#pragma unroll
                for (int u = 0; u < 4; u++) {
                    s[j * 4 + u] *= egv;
                    kv += kr[j * 4 + u] * s[j * 4 + u];
                }
            }
            kv += __shfl_xor_sync(~0u, kv, 16);
            float vn = (vt - kv) * bt;
            float ov = 0.f;
#pragma unroll
            for (int j = 0; j < 8; j++) {
                float4 qq = *(const float4*)&sq[tl][half * 32 + j * 4];
                float qv[4] = {qq.x, qq.y, qq.z, qq.w};
#pragma unroll
                for (int u = 0; u < 4; u++) {
                    s[j * 4 + u] += kr[j * 4 + u] * vn;
                    ov += qv[u] * s[j * 4 + u];
                }
            }
            ov += __shfl_xor_sync(~0u, ov, 16);
            if (half == 0) o[(size_t)t * VAL + h * DV + col] = ov;
        }
    }
}

// ---------------- gated RMSNorm on heads + silu(gate) ----------------
__global__ void gated_norm_kernel(const float* __restrict__ o, const float* __restrict__ gate,
                                  const float* __restrict__ onw, float* __restrict__ og) {
    int gw = blockIdx.x * 4 + (threadIdx.x >> 5);   // warp per (t,h)
    int lane = threadIdx.x & 31;
    int t = gw >> 4, h = gw & 15;
    const float* orow = o + (size_t)t * VAL + h * DV;
    float vv[4]; float ss = 0.f;
#pragma unroll
    for (int i = 0; i < 4; i++) { vv[i] = orow[lane + i * 32]; ss += vv[i] * vv[i]; }
    for (int off = 16; off > 0; off >>= 1) ss += __shfl_xor_sync(~0u, ss, off);
    float sc = rsqrtf(ss * (1.f / DV) + 1e-5f);
#pragma unroll
    for (int i = 0; i < 4; i++) {
        int dv = lane + i * 32;
        float gt = gate[(size_t)t * VAL + h * DV + dv];
        og[(size_t)t * VAL + h * DV + dv] = vv[i] * sc * onw[dv] * (gt / (1.f + expf(-gt)));
    }
}

// ---------------- launch ----------------
extern "C" void kernel_launch(void* const* d_in, const int* in_sizes, int n_in,
                              void* d_out, int out_size) {
    const float* hs       = (const float*)d_in[0];
    const float* norm_w   = (const float*)d_in[1];
    const float* q_w      = (const float*)d_in[2];
    const float* k_w      = (const float*)d_in[3];
    const float* v_w      = (const float*)d_in[4];
    const float* a_w      = (const float*)d_in[5];
    const float* b_w      = (const float*)d_in[6];
    const float* g_w      = (const float*)d_in[7];
    const float* dt_bias  = (const float*)d_in[8];
    const float* A_log    = (const float*)d_in[9];
    const float* conv_q_w = (const float*)d_in[10];
    const float* conv_k_w = (const float*)d_in[11];
    const float* conv_v_w = (const float*)d_in[12];
    const float* o_norm_w = (const float*)d_in[13];
    const float* o_proj_w = (const float*)d_in[14];
    const float* out_proj_w = (const float*)d_in[15];
    float* out = (float*)d_out;

    float *xn, *qpre, *kpre, *vpre, *gate, *qb, *kb, *vb;
    float *araw, *braw, *beta, *eg, *ob, *og, *t1;
    cudaGetSymbolAddress((void**)&xn,   g_xn);
    cudaGetSymbolAddress((void**)&qpre, g_qpre);
    cudaGetSymbolAddress((void**)&kpre, g_kpre);
    cudaGetSymbolAddress((void**)&vpre, g_vpre);
    cudaGetSymbolAddress((void**)&gate, g_gate);
    cudaGetSymbolAddress((void**)&qb,   g_q);
    cudaGetSymbolAddress((void**)&kb,   g_k);
    cudaGetSymbolAddress((void**)&vb,   g_v);
    cudaGetSymbolAddress((void**)&araw, g_araw);
    cudaGetSymbolAddress((void**)&braw, g_braw);
    cudaGetSymbolAddress((void**)&beta, g_beta);
    cudaGetSymbolAddress((void**)&eg,   g_eg);
    cudaGetSymbolAddress((void**)&ob,   g_o);
    cudaGetSymbolAddress((void**)&og,   g_og);
    cudaGetSymbolAddress((void**)&t1,   g_t1);

    // 1. RMSNorm
    rmsnorm_kernel<<<TT, 256>>>(hs, norm_w, xn);

    // 2. projections
    sgemm_nt<<<dim3(HID / BN, TT / BM), 256>>>(xn, q_w, qpre, TT, HID, HID);
    sgemm_nt<<<dim3(HID / BN, TT / BM), 256>>>(xn, k_w, kpre, TT, HID, HID);
    sgemm_nt<<<dim3(VAL / BN, TT / BM), 256>>>(xn, v_w, vpre, TT, VAL, HID);
    sgemm_nt<<<dim3(VAL / BN, TT / BM), 256>>>(xn, g_w, gate, TT, VAL, HID);
    proj16_kernel<<<(TT * NH) / 8, 256>>>(xn, a_w, araw);
    proj16_kernel<<<(TT * NH) / 8, 256>>>(xn, b_w, braw);

    // 3. scalar gates
    gate_scalar_kernel<<<(TT * NH + 255) / 256, 256>>>(araw, braw, dt_bias, A_log, beta, eg);

    // 4. convs + q/k postproc
    conv_qk_kernel<<<(TT * NH) / 4, 128>>>(qpre, conv_q_w, qb, 0);
    conv_qk_kernel<<<(TT * NH) / 4, 128>>>(kpre, conv_k_w, kb, 1);
    conv_v_kernel<<<(TT * VAL) / 256, 256>>>(vpre, conv_v_w, vb);

    // 5. scan
    scan_kernel<<<32, 128>>>(qb, kb, vb, beta, eg, ob);

    // 6. gated norm
    gated_norm_kernel<<<(TT * NH) / 4, 128>>>(ob, gate, o_norm_w, og);

    // 7. output projections
    sgemm_nt<<<dim3(HID / BN, TT / BM), 256>>>(og, o_proj_w, t1, TT, HID, VAL);
    sgemm_nt<<<dim3(HID / BN, TT / BM), 256>>>(t1, out_proj_w, out, TT, HID, HID);
}

// round 3
// speedup vs baseline: 1.4904x; 1.4904x over previous
#include <cuda_runtime.h>
#include <cuda_bf16.h>
#include <math.h>
#include <stdint.h>

// ---------------- problem constants ----------------
#define TT   2048
#define HID  1024
#define NH   16
#define DK   64
#define DV   128
#define VAL  2048   // NH*DV
#define CONV 4

// ---------------- scratch (__device__ globals; no allocation allowed) ----------------
__device__ __align__(16) float g_xn  [TT * HID];
__device__ __align__(16) float g_qpre[TT * HID];
__device__ __align__(16) float g_kpre[TT * HID];
__device__ __align__(16) float g_vpre[TT * VAL];
__device__ __align__(16) float g_gate[TT * VAL];
__device__ __align__(16) float g_q   [TT * HID];
__device__ __align__(16) float g_k   [TT * HID];
__device__ __align__(16) float g_v   [TT * VAL];
__device__ __align__(16) float g_beta[TT * NH];
__device__ __align__(16) float g_eg  [TT * NH];
__device__ __align__(16) float g_o   [TT * VAL];
__device__ __align__(16) float g_og  [TT * VAL];
__device__ __align__(16) float g_t1  [TT * HID];

// ---------------- helpers ----------------
__device__ __forceinline__ uint32_t f2tf32(float f) {
    uint32_t r;
    asm("cvt.rna.tf32.f32 %0, %1;" : "=r"(r) : "f"(f));
    return r;
}
#define CP_ASYNC16(dst, src) \
    asm volatile("cp.async.cg.shared.global [%0], [%1], 16;" :: "r"(dst), "l"(src))
#define CP_COMMIT() asm volatile("cp.async.commit_group;")
#define CP_WAIT1()  asm volatile("cp.async.wait_group 1;")
#define CP_WAIT0()  asm volatile("cp.async.wait_group 0;")

// ---------------- RMSNorm ----------------
__global__ void rmsnorm_kernel(const float* __restrict__ x, const float* __restrict__ w,
                               float* __restrict__ y) {
    int row = blockIdx.x;
    int tid = threadIdx.x;                 // 256
    const float* xr = x + (size_t)row * HID;
    float v[4];
    float s = 0.f;
#pragma unroll
    for (int i = 0; i < 4; i++) { v[i] = xr[tid + i * 256]; s += v[i] * v[i]; }
    __shared__ float red[256];
    red[tid] = s; __syncthreads();
    for (int o = 128; o > 0; o >>= 1) { if (tid < o) red[tid] += red[tid + o]; __syncthreads(); }
    float scale = rsqrtf(red[0] * (1.f / HID) + 1e-6f);
#pragma unroll
    for (int i = 0; i < 4; i++)
        y[(size_t)row * HID + tid + i * 256] = v[i] * scale * w[tid + i * 256];
}

// ---------------- tf32 tensor-core GEMM: C[M,N] = A[M,K] @ W[N,K]^T ----------------
// 128x128x32 tiles, 256 threads (8 warps, 2x4), warp tile 64x32.
// Smem holds A/B tiles in mma fragment-register order:
//   A: [mf(8)][ks(4)][reg(4)][lane(32)]  B: [nf(16)][ks(4)][reg(2)][lane(32)]
// so each gmem float4 is one contiguous 16B cp.async chunk, and fragment
// loads are conflict-free stride-32 LDS.32.
#define A_TILE_F 4096   // 8*4*4*32
#define B_TILE_F 4096   // 16*4*2*32
__global__ __launch_bounds__(256) void tf32_gemm(const float* __restrict__ A,
                                                 const float* __restrict__ W,
                                                 float* __restrict__ C,
                                                 int M, int N, int K) {
    extern __shared__ float smem[];
    float* As = smem;                       // [2][A_TILE_F]
    float* Bs = smem + 2 * A_TILE_F;        // [2][B_TILE_F]

    const int tid  = threadIdx.x;
    const int lane = tid & 31;
    const int warp = tid >> 5;
    const int wm   = warp & 1;              // 0..1
    const int wn   = warp >> 1;             // 0..3
    const int bm   = blockIdx.y * 128;
    const int bn   = blockIdx.x * 128;

    float acc[4][4][4];
#pragma unroll
    for (int i = 0; i < 4; i++)
#pragma unroll
        for (int j = 0; j < 4; j++)
#pragma unroll
            for (int r = 0; r < 4; r++) acc[i][j][r] = 0.f;

    // precompute per-thread load descriptors
    uint32_t smem_base = (uint32_t)__cvta_generic_to_shared(smem);
    int m_[4], q_[4];
#pragma unroll
    for (int p = 0; p < 4; p++) { int idx = tid + p * 256; m_[p] = idx >> 3; q_[p] = idx & 7; }

    auto load_tile = [&](int t, int buf) {
#pragma unroll
        for (int p = 0; p < 4; p++) {
            int m = m_[p], q = q_[p];
            // A chunk: rows bm+m, k = t*32 + q*4
            int mf = m >> 4, mrow = m & 15, ks = q >> 1;
            int regA = (mrow >> 3) + ((q & 1) << 1);
            uint32_t dstA = smem_base +
                (uint32_t)(buf * A_TILE_F + ((mf * 4 + ks) * 4 + regA) * 32 + (mrow & 7) * 4) * 4u;
            CP_ASYNC16(dstA, A + (size_t)(bm + m) * K + t * 32 + q * 4);
            // B chunk: rows bn+m (n index), same k
            int nf = m >> 3, nrow = m & 7;
            int regB = (q & 1);
            uint32_t dstB = smem_base +
                (uint32_t)(2 * A_TILE_F + buf * B_TILE_F + ((nf * 4 + ks) * 2 + regB) * 32 + nrow * 4) * 4u;
            CP_ASYNC16(dstB, W + (size_t)(bn + m) * K + t * 32 + q * 4);
        }
    };

    const int NT = K >> 5;
    load_tile(0, 0); CP_COMMIT();

    for (int t = 0; t < NT; t++) {
        if (t + 1 < NT) { load_tile(t + 1, (t + 1) & 1); CP_COMMIT(); CP_WAIT1(); }
        else           { CP_WAIT0(); }
        __syncthreads();

        const float* Ab = As + (t & 1) * A_TILE_F;
        const float* Bb = Bs + (t & 1) * B_TILE_F;
#pragma unroll
        for (int ks = 0; ks < 4; ks++) {
            uint32_t a[4][4], b[4][2];
#pragma unroll
            for (int mf = 0; mf < 4; mf++) {
                int base = (((wm * 4 + mf) * 4 + ks) * 4) * 32 + lane;
#pragma unroll
                for (int r = 0; r < 4; r++) a[mf][r] = f2tf32(Ab[base + r * 32]);
            }
#pragma unroll
            for (int nf = 0; nf < 4; nf++) {
                int base = (((wn * 4 + nf) * 4 + ks) * 2) * 32 + lane;
#pragma unroll
                for (int r = 0; r < 2; r++) b[nf][r] = f2tf32(Bb[base + r * 32]);
            }
#pragma unroll
            for (int mf = 0; mf < 4; mf++)
#pragma unroll
                for (int nf = 0; nf < 4; nf++) {
                    asm volatile(
                        "mma.sync.aligned.m16n8k8.row.col.f32.tf32.tf32.f32 "
                        "{%0,%1,%2,%3}, {%4,%5,%6,%7}, {%8,%9}, {%0,%1,%2,%3};"
                        : "+f"(acc[mf][nf][0]), "+f"(acc[mf][nf][1]),
                          "+f"(acc[mf][nf][2]), "+f"(acc[mf][nf][3])
                        : "r"(a[mf][0]), "r"(a[mf][1]), "r"(a[mf][2]), "r"(a[mf][3]),
                          "r"(b[nf][0]), "r"(b[nf][1]));
                }
        }
        __syncthreads();
    }

    // epilogue
    const int row0 = bm + wm * 64 + (lane >> 2);
    const int col0 = bn + wn * 32 + (lane & 3) * 2;
#pragma unroll
    for (int mf = 0; mf < 4; mf++)
#pragma unroll
        for (int nf = 0; nf < 4; nf++) {
            int r = row0 + mf * 16;
            int c = col0 + nf * 8;
            float2 v0 = make_float2(acc[mf][nf][0], acc[mf][nf][1]);
            float2 v1 = make_float2(acc[mf][nf][2], acc[mf][nf][3]);
            *(float2*)(C + (size_t)r * N + c)       = v0;
            *(float2*)(C + (size_t)(r + 8) * N + c) = v1;
        }
}

// ---------------- fused a/b thin projections + gate scalars ----------------
// warp per (t,h): beta = sigmoid(x.b_w), eg = exp(-exp(A_log)*softplus(x.a_w + dt_bias))
__global__ void proj_ab_kernel(const float* __restrict__ X,
                               const float* __restrict__ a_w, const float* __restrict__ b_w,
                               const float* __restrict__ dt_bias, const float* __restrict__ A_log,
                               float* __restrict__ beta, float* __restrict__ eg) {
    int gw = blockIdx.x * 8 + (threadIdx.x >> 5);
    int lane = threadIdx.x & 31;
    int m = gw >> 4, h = gw & 15;
    const float4* xr = (const float4*)(X + (size_t)m * HID);
    const float4* ar = (const float4*)(a_w + (size_t)h * HID);
    const float4* br = (const float4*)(b_w + (size_t)h * HID);
    float sa = 0.f, sb = 0.f;
#pragma unroll
    for (int i = 0; i < 8; i++) {
        float4 x4 = xr[lane + i * 32];
        float4 a4 = ar[lane + i * 32];
        float4 b4 = br[lane + i * 32];
        sa += x4.x * a4.x + x4.y * a4.y + x4.z * a4.z + x4.w * a4.w;
        sb += x4.x * b4.x + x4.y * b4.y + x4.z * b4.z + x4.w * b4.w;
    }
    for (int o = 16; o > 0; o >>= 1) {
        sa += __shfl_xor_sync(~0u, sa, o);
        sb += __shfl_xor_sync(~0u, sb, o);
    }
    if (lane == 0) {
        beta[m * NH + h] = 1.f / (1.f + expf(-sb));
        float xv = sa + dt_bias[h];
        float sp = (xv > 20.f) ? xv : log1pf(expf(xv));
        eg[m * NH + h] = expf(-expf(A_log[h]) * sp);
    }
}

// ---------------- causal depthwise conv(K=4)+silu then per-head postproc for q/k ----------------
__global__ void conv_qk_kernel(const float* __restrict__ pre, const float* __restrict__ cw,
                               float* __restrict__ out, int kmode) {
    int gw = blockIdx.x * 4 + (threadIdx.x >> 5);
    int lane = threadIdx.x & 31;
    int t = gw >> 4, h = gw & 15;
    float y[2];
#pragma unroll
    for (int e = 0; e < 2; e++) {
        int d = lane + e * 32;
        int c = h * DK + d;
        float acc = 0.f;
#pragma unroll
        for (int i = 0; i < CONV; i++) {
            int tt = t - (CONV - 1) + i;
            float xv = (tt >= 0) ? pre[(size_t)tt * HID + c] : 0.f;
            acc += xv * cw[c * CONV + i];
        }
        y[e] = acc / (1.f + expf(-acc));   // silu
    }
    if (kmode) {                           // DC removal: subtract per-head mean
        float m = y[0] + y[1];
        for (int o = 16; o > 0; o >>= 1) m += __shfl_xor_sync(~0u, m, o);
        m *= (1.f / DK);
        y[0] -= m; y[1] -= m;
    }
    float ss = y[0] * y[0] + y[1] * y[1];
    for (int o = 16; o > 0; o >>= 1) ss += __shfl_xor_sync(~0u, ss, o);
    float sc = rsqrtf(ss + 1e-6f);
    if (!kmode) sc *= 0.125f;              // DK^-0.5
#pragma unroll
    for (int e = 0; e < 2; e++) {
        int d = lane + e * 32;
        out[(size_t)t * HID + h * DK + d] = y[e] * sc;
    }
}

// ---------------- causal depthwise conv(K=4)+silu for v ----------------
__global__ void conv_v_kernel(const float* __restrict__ pre, const float* __restrict__ cw,
                              float* __restrict__ out) {
    int i = blockIdx.x * blockDim.x + threadIdx.x;
    if (i >= TT * VAL) return;
    int t = i >> 11, c = i & (VAL - 1);
    float acc = 0.f;
#pragma unroll
    for (int j = 0; j < CONV; j++) {
        int tt = t - (CONV - 1) + j;
        float xv = (tt >= 0) ? pre[(size_t)tt * VAL + c] : 0.f;
        acc += xv * cw[c * CONV + j];
    }
    out[i] = acc / (1.f + expf(-acc));
}

// ---------------- gated delta-rule scan ----------------
__global__ __launch_bounds__(128) void scan_kernel(const float* __restrict__ q,
                                                   const float* __restrict__ k,
                                                   const float* __restrict__ v,
                                                   const float* __restrict__ beta,
                                                   const float* __restrict__ eg,
                                                   float* __restrict__ o) {
    const int h = blockIdx.x >> 1;
    const int colbase = (blockIdx.x & 1) * 64;
    const int tid = threadIdx.x;
    const int warp = tid >> 5, lane = tid & 31;
    const int col = colbase + warp * 16 + (lane & 15);
    const int half = lane >> 4;
    __shared__ float sk[64][64];
    __shared__ float sq[64][64];
    __shared__ float sb[64], se[64];
    float s[32];
#pragma unroll
    for (int i = 0; i < 32; i++) s[i] = 0.f;

    for (int c0 = 0; c0 < TT; c0 += 64) {
        __syncthreads();
#pragma unroll
        for (int i = 0; i < 8; i++) {
            int idx = tid + i * 128;
            int tl = idx >> 4, f4 = idx & 15;
            float4 kk = *(const float4*)(k + (size_t)(c0 + tl) * HID + h * DK + f4 * 4);
            *(float4*)&sk[tl][f4 * 4] = kk;
            float4 qq = *(const float4*)(q + (size_t)(c0 + tl) * HID + h * DK + f4 * 4);
            *(float4*)&sq[tl][f4 * 4] = qq;
        }
        if (tid < 64) {
            sb[tid] = beta[(size_t)(c0 + tid) * NH + h];
            se[tid] = eg[(size_t)(c0 + tid) * NH + h];
        }
        __syncthreads();
        for (int tl = 0; tl < 64; tl++) {
            int t = c0 + tl;
            float egv = se[tl], bt = sb[tl];
            float vt = v[(size_t)t * VAL + h * DV + col];
            float kr[32];
            float kv = 0.f;
#pragma unroll
            for (int j = 0; j < 8; j++) {
                float4 kk = *(const float4*)&sk[tl][half * 32 + j * 4];
                kr[j * 4 + 0] = kk.x; kr[j * 4 + 1] = kk.y;
                kr[j * 4 + 2] = kk.z; kr[j * 4 + 3] = kk.w;
#pragma unroll
                for (int u = 0; u < 4; u++) {
                    s[j * 4 + u] *= egv;
                    kv += kr[j * 4 + u] * s[j * 4 + u];
                }
            }
            kv += __shfl_xor_sync(~0u, kv, 16);
            float vn = (vt - kv) * bt;
            float ov = 0.f;
#pragma unroll
            for (int j = 0; j < 8; j++) {
                float4 qq = *(const float4*)&sq[tl][half * 32 + j * 4];
                float qv[4] = {qq.x, qq.y, qq.z, qq.w};
#pragma unroll
                for (int u = 0; u < 4; u++) {
                    s[j * 4 + u] += kr[j * 4 + u] * vn;
                    ov += qv[u] * s[j * 4 + u];
                }
            }
            ov += __shfl_xor_sync(~0u, ov, 16);
            if (half == 0) o[(size_t)t * VAL + h * DV + col] = ov;
        }
    }
}

// ---------------- gated RMSNorm on heads + silu(gate) ----------------
__global__ void gated_norm_kernel(const float* __restrict__ o, const float* __restrict__ gate,
                                  const float* __restrict__ onw, float* __restrict__ og) {
    int gw = blockIdx.x * 4 + (threadIdx.x >> 5);   // warp per (t,h)
    int lane = threadIdx.x & 31;
    int t = gw >> 4, h = gw & 15;
    const float* orow = o + (size_t)t * VAL + h * DV;
    float vv[4]; float ss = 0.f;
#pragma unroll
    for (int i = 0; i < 4; i++) { vv[i] = orow[lane + i * 32]; ss += vv[i] * vv[i]; }
    for (int off = 16; off > 0; off >>= 1) ss += __shfl_xor_sync(~0u, ss, off);
    float sc = rsqrtf(ss * (1.f / DV) + 1e-5f);
#pragma unroll
    for (int i = 0; i < 4; i++) {
        int dv = lane + i * 32;
        float gt = gate[(size_t)t * VAL + h * DV + dv];
        og[(size_t)t * VAL + h * DV + dv] = vv[i] * sc * onw[dv] * (gt / (1.f + expf(-gt)));
    }
}

// ---------------- launch ----------------
extern "C" void kernel_launch(void* const* d_in, const int* in_sizes, int n_in,
                              void* d_out, int out_size) {
    const float* hs       = (const float*)d_in[0];
    const float* norm_w   = (const float*)d_in[1];
    const float* q_w      = (const float*)d_in[2];
    const float* k_w      = (const float*)d_in[3];
    const float* v_w      = (const float*)d_in[4];
    const float* a_w      = (const float*)d_in[5];
    const float* b_w      = (const float*)d_in[6];
    const float* g_w      = (const float*)d_in[7];
    const float* dt_bias  = (const float*)d_in[8];
    const float* A_log    = (const float*)d_in[9];
    const float* conv_q_w = (const float*)d_in[10];
    const float* conv_k_w = (const float*)d_in[11];
    const float* conv_v_w = (const float*)d_in[12];
    const float* o_norm_w = (const float*)d_in[13];
    const float* o_proj_w = (const float*)d_in[14];
    const float* out_proj_w = (const float*)d_in[15];
    float* out = (float*)d_out;

    float *xn, *qpre, *kpre, *vpre, *gate, *qb, *kb, *vb;
    float *beta, *eg, *ob, *og, *t1;
    cudaGetSymbolAddress((void**)&xn,   g_xn);
    cudaGetSymbolAddress((void**)&qpre, g_qpre);
    cudaGetSymbolAddress((void**)&kpre, g_kpre);
    cudaGetSymbolAddress((void**)&vpre, g_vpre);
    cudaGetSymbolAddress((void**)&gate, g_gate);
    cudaGetSymbolAddress((void**)&qb,   g_q);
    cudaGetSymbolAddress((void**)&kb,   g_k);
    cudaGetSymbolAddress((void**)&vb,   g_v);
    cudaGetSymbolAddress((void**)&beta, g_beta);
    cudaGetSymbolAddress((void**)&eg,   g_eg);
    cudaGetSymbolAddress((void**)&ob,   g_o);
    cudaGetSymbolAddress((void**)&og,   g_og);
    cudaGetSymbolAddress((void**)&t1,   g_t1);

    static bool attr_set = false;
    if (!attr_set) {
        cudaFuncSetAttribute(tf32_gemm, cudaFuncAttributeMaxDynamicSharedMemorySize,
                             (2 * A_TILE_F + 2 * B_TILE_F) * 4);
        attr_set = true;
    }
    const int smem_bytes = (2 * A_TILE_F + 2 * B_TILE_F) * 4;

    // 1. RMSNorm
    rmsnorm_kernel<<<TT, 256>>>(hs, norm_w, xn);

    // 2. projections (tensor core tf32)
    tf32_gemm<<<dim3(HID / 128, TT / 128), 256, smem_bytes>>>(xn, q_w, qpre, TT, HID, HID);
    tf32_gemm<<<dim3(HID / 128, TT / 128), 256, smem_bytes>>>(xn, k_w, kpre, TT, HID, HID);
    tf32_gemm<<<dim3(VAL / 128, TT / 128), 256, smem_bytes>>>(xn, v_w, vpre, TT, VAL, HID);
    tf32_gemm<<<dim3(VAL / 128, TT / 128), 256, smem_bytes>>>(xn, g_w, gate, TT, VAL, HID);
    proj_ab_kernel<<<(TT * NH) / 8, 256>>>(xn, a_w, b_w, dt_bias, A_log, beta, eg);

    // 3. convs + q/k postproc
    conv_qk_kernel<<<(TT * NH) / 4, 128>>>(qpre, conv_q_w, qb, 0);
    conv_qk_kernel<<<(TT * NH) / 4, 128>>>(kpre, conv_k_w, kb, 1);
    conv_v_kernel<<<(TT * VAL) / 256, 256>>>(vpre, conv_v_w, vb);

    // 4. scan
    scan_kernel<<<32, 128>>>(qb, kb, vb, beta, eg, ob);

    // 5. gated norm
    gated_norm_kernel<<<(TT * NH) / 4, 128>>>(ob, gate, o_norm_w, og);

    // 6. output projections
    tf32_gemm<<<dim3(HID / 128, TT / 128), 256, smem_bytes>>>(og, o_proj_w, t1, TT, HID, VAL);
    tf32_gemm<<<dim3(HID / 128, TT / 128), 256, smem_bytes>>>(t1, out_proj_w, out, TT, HID, HID);
}

// round 5
// speedup vs baseline: 2.1178x; 1.4210x over previous
#include <cuda_runtime.h>
#include <cuda_bf16.h>
#include <math.h>
#include <stdint.h>

// ---------------- problem constants ----------------
#define TT   2048
#define HID  1024
#define NH   16
#define DK   64
#define DV   128
#define VAL  2048   // NH*DV
#define CONV 4

// ---------------- scratch ----------------
__device__ __align__(16) float g_xn  [TT * HID];
__device__ __align__(16) float g_qpre[TT * HID];
__device__ __align__(16) float g_kpre[TT * HID];
__device__ __align__(16) float g_vpre[TT * VAL];
__device__ __align__(16) float g_gate[TT * VAL];
__device__ __align__(16) float g_q   [TT * HID];
__device__ __align__(16) float g_k   [TT * HID];
__device__ __align__(16) float g_v   [TT * VAL];
__device__ __align__(16) float g_beta[TT * NH];
__device__ __align__(16) float g_eg  [TT * NH];
__device__ __align__(16) float g_o   [TT * VAL];
__device__ __align__(16) float g_og  [TT * VAL];
__device__ __align__(16) float g_t1  [TT * HID];

// ---------------- helpers ----------------
__device__ __forceinline__ uint32_t f2tf32(float f) {
    uint32_t r;
    asm("cvt.rna.tf32.f32 %0, %1;" : "=r"(r) : "f"(f));
    return r;
}
__device__ __forceinline__ uint32_t smaddr(const void* p) {
    return (uint32_t)__cvta_generic_to_shared(p);
}
#define CP_ASYNC16(dst, src) \
    asm volatile("cp.async.cg.shared.global [%0], [%1], 16;" :: "r"(dst), "l"(src))
#define CP_ASYNC4(dst, src) \
    asm volatile("cp.async.ca.shared.global [%0], [%1], 4;" :: "r"(dst), "l"(src))
#define CP_COMMIT() asm volatile("cp.async.commit_group;")
#define CP_WAIT1()  asm volatile("cp.async.wait_group 1;")
#define CP_WAIT0()  asm volatile("cp.async.wait_group 0;")

// ---------------- RMSNorm ----------------
__global__ void rmsnorm_kernel(const float* __restrict__ x, const float* __restrict__ w,
                               float* __restrict__ y) {
    int row = blockIdx.x;
    int tid = threadIdx.x;
    const float* xr = x + (size_t)row * HID;
    float v[4];
    float s = 0.f;
#pragma unroll
    for (int i = 0; i < 4; i++) { v[i] = xr[tid + i * 256]; s += v[i] * v[i]; }
    __shared__ float red[256];
    red[tid] = s; __syncthreads();
    for (int o = 128; o > 0; o >>= 1) { if (tid < o) red[tid] += red[tid + o]; __syncthreads(); }
    float scale = rsqrtf(red[0] * (1.f / HID) + 1e-6f);
#pragma unroll
    for (int i = 0; i < 4; i++)
        y[(size_t)row * HID + tid + i * 256] = v[i] * scale * w[tid + i * 256];
}

// ---------------- tf32 tensor-core GEMM body: C[bm:,bn:] += A @ W^T ----------------
// 128x128x32 tiles, 256 threads (8 warps 2x4), warp tile 64x32, 3-stage cp.async.
// Smem fragment-register order: A [mf(8)][ks(4)][reg(4)][lane(32)], B [nf(16)][ks(4)][reg(2)][lane(32)]
#define A_TILE_F 4096
#define B_TILE_F 4096
#define GEMM_SMEM_BYTES (3 * (A_TILE_F + B_TILE_F) * 4)

__device__ __forceinline__ void gemm_body(const float* __restrict__ A,
                                          const float* __restrict__ W,
                                          float* __restrict__ C,
                                          int N, int K, int bm, int bn, float* smem) {
    const int tid  = threadIdx.x;
    const int lane = tid & 31;
    const int warp = tid >> 5;
    const int wm   = warp & 1;
    const int wn   = warp >> 1;

    float acc[4][4][4];
#pragma unroll
    for (int i = 0; i < 4; i++)
#pragma unroll
        for (int j = 0; j < 4; j++)
#pragma unroll
            for (int r = 0; r < 4; r++) acc[i][j][r] = 0.f;

    uint32_t smem_base = smaddr(smem);
    int m_[4], q_[4];
#pragma unroll
    for (int p = 0; p < 4; p++) { int idx = tid + p * 256; m_[p] = idx >> 3; q_[p] = idx & 7; }

    auto load_tile = [&](int t, int buf) {
#pragma unroll
        for (int p = 0; p < 4; p++) {
            int m = m_[p], q = q_[p];
            int mf = m >> 4, mrow = m & 15, ks = q >> 1;
            int regA = (mrow >> 3) + ((q & 1) << 1);
            uint32_t dstA = smem_base +
                (uint32_t)(buf * A_TILE_F + ((mf * 4 + ks) * 4 + regA) * 32 + (mrow & 7) * 4) * 4u;
            CP_ASYNC16(dstA, A + (size_t)(bm + m) * K + t * 32 + q * 4);
            int nf = m >> 3, nrow = m & 7;
            int regB = (q & 1);
            uint32_t dstB = smem_base +
                (uint32_t)(3 * A_TILE_F + buf * B_TILE_F + ((nf * 4 + ks) * 2 + regB) * 32 + nrow * 4) * 4u;
            CP_ASYNC16(dstB, W + (size_t)(bn + m) * K + t * 32 + q * 4);
        }
    };

    const int NT = K >> 5;
    load_tile(0, 0); CP_COMMIT();
    load_tile(1, 1); CP_COMMIT();

    for (int t = 0; t < NT; t++) {
        if (t + 1 < NT) CP_WAIT1(); else CP_WAIT0();
        __syncthreads();
        if (t + 2 < NT) { load_tile(t + 2, (t + 2) % 3); CP_COMMIT(); }

        int buf = t % 3;
        const float* Ab = smem + buf * A_TILE_F;
        const float* Bb = smem + 3 * A_TILE_F + buf * B_TILE_F;
#pragma unroll
        for (int ks = 0; ks < 4; ks++) {
            uint32_t a[4][4], b[4][2];
#pragma unroll
            for (int mf = 0; mf < 4; mf++) {
                int base = (((wm * 4 + mf) * 4 + ks) * 4) * 32 + lane;
#pragma unroll
                for (int r = 0; r < 4; r++) a[mf][r] = f2tf32(Ab[base + r * 32]);
            }
#pragma unroll
            for (int nf = 0; nf < 4; nf++) {
                int base = (((wn * 4 + nf) * 4 + ks) * 2) * 32 + lane;
#pragma unroll
                for (int r = 0; r < 2; r++) b[nf][r] = f2tf32(Bb[base + r * 32]);
            }
#pragma unroll
            for (int mf = 0; mf < 4; mf++)
#pragma unroll
                for (int nf = 0; nf < 4; nf++) {
                    asm volatile(
                        "mma.sync.aligned.m16n8k8.row.col.f32.tf32.tf32.f32 "
                        "{%0,%1,%2,%3}, {%4,%5,%6,%7}, {%8,%9}, {%0,%1,%2,%3};"
                        : "+f"(acc[mf][nf][0]), "+f"(acc[mf][nf][1]),
                          "+f"(acc[mf][nf][2]), "+f"(acc[mf][nf][3])
                        : "r"(a[mf][0]), "r"(a[mf][1]), "r"(a[mf][2]), "r"(a[mf][3]),
                          "r"(b[nf][0]), "r"(b[nf][1]));
                }
        }
    }

    const int row0 = bm + wm * 64 + (lane >> 2);
    const int col0 = bn + wn * 32 + (lane & 3) * 2;
#pragma unroll
    for (int mf = 0; mf < 4; mf++)
#pragma unroll
        for (int nf = 0; nf < 4; nf++) {
            int r = row0 + mf * 16;
            int c = col0 + nf * 8;
            float2 v0 = make_float2(acc[mf][nf][0], acc[mf][nf][1]);
            float2 v1 = make_float2(acc[mf][nf][2], acc[mf][nf][3]);
            *(float2*)(C + (size_t)r * N + c)       = v0;
            *(float2*)(C + (size_t)(r + 8) * N + c) = v1;
        }
}

__global__ __launch_bounds__(256) void tf32_gemm(const float* __restrict__ A,
                                                 const float* __restrict__ W,
                                                 float* __restrict__ C, int N, int K) {
    extern __shared__ float smem[];
    gemm_body(A, W, C, N, K, blockIdx.y * 128, blockIdx.x * 128, smem);
}

// fused q/k/v/g projection: 48 N-tiles (q:0-7, k:8-15, v:16-31, g:32-47), all K=HID
__global__ __launch_bounds__(256) void qkvg_gemm(const float* __restrict__ xn,
                                                 const float* __restrict__ qw,
                                                 const float* __restrict__ kw,
                                                 const float* __restrict__ vw,
                                                 const float* __restrict__ gw,
                                                 float* __restrict__ qo, float* __restrict__ ko,
                                                 float* __restrict__ vo, float* __restrict__ go) {
    extern __shared__ float smem[];
    int nt = blockIdx.x;
    const float* W; float* C; int N, bn;
    if (nt < 8)       { W = qw; C = qo; N = HID; bn = nt << 7; }
    else if (nt < 16) { W = kw; C = ko; N = HID; bn = (nt - 8) << 7; }
    else if (nt < 32) { W = vw; C = vo; N = VAL; bn = (nt - 16) << 7; }
    else              { W = gw; C = go; N = VAL; bn = (nt - 32) << 7; }
    gemm_body(xn, W, C, N, HID, blockIdx.y * 128, bn, smem);
}

// ---------------- fused a/b thin projections + gate scalars ----------------
__global__ void proj_ab_kernel(const float* __restrict__ X,
                               const float* __restrict__ a_w, const float* __restrict__ b_w,
                               const float* __restrict__ dt_bias, const float* __restrict__ A_log,
                               float* __restrict__ beta, float* __restrict__ eg) {
    int gw = blockIdx.x * 8 + (threadIdx.x >> 5);
    int lane = threadIdx.x & 31;
    int m = gw >> 4, h = gw & 15;
    const float4* xr = (const float4*)(X + (size_t)m * HID);
    const float4* ar = (const float4*)(a_w + (size_t)h * HID);
    const float4* br = (const float4*)(b_w + (size_t)h * HID);
    float sa = 0.f, sb = 0.f;
#pragma unroll
    for (int i = 0; i < 8; i++) {
        float4 x4 = xr[lane + i * 32];
        float4 a4 = ar[lane + i * 32];
        float4 b4 = br[lane + i * 32];
        sa += x4.x * a4.x + x4.y * a4.y + x4.z * a4.z + x4.w * a4.w;
        sb += x4.x * b4.x + x4.y * b4.y + x4.z * b4.z + x4.w * b4.w;
    }
    for (int o = 16; o > 0; o >>= 1) {
        sa += __shfl_xor_sync(~0u, sa, o);
        sb += __shfl_xor_sync(~0u, sb, o);
    }
    if (lane == 0) {
        beta[m * NH + h] = 1.f / (1.f + expf(-sb));
        float xv = sa + dt_bias[h];
        float sp = (xv > 20.f) ? xv : log1pf(expf(xv));
        eg[m * NH + h] = expf(-expf(A_log[h]) * sp);
    }
}

// ---------------- conv(K=4)+silu + per-head postproc for q/k ----------------
__global__ void conv_qk_kernel(const float* __restrict__ pre, const float* __restrict__ cw,
                               float* __restrict__ out, int kmode) {
    int gw = blockIdx.x * 4 + (threadIdx.x >> 5);
    int lane = threadIdx.x & 31;
    int t = gw >> 4, h = gw & 15;
    float y[2];
#pragma unroll
    for (int e = 0; e < 2; e++) {
        int d = lane + e * 32;
        int c = h * DK + d;
        float acc = 0.f;
#pragma unroll
        for (int i = 0; i < CONV; i++) {
            int tt = t - (CONV - 1) + i;
            float xv = (tt >= 0) ? pre[(size_t)tt * HID + c] : 0.f;
            acc += xv * cw[c * CONV + i];
        }
        y[e] = acc / (1.f + expf(-acc));
    }
    if (kmode) {
        float m = y[0] + y[1];
        for (int o = 16; o > 0; o >>= 1) m += __shfl_xor_sync(~0u, m, o);
        m *= (1.f / DK);
        y[0] -= m; y[1] -= m;
    }
    float ss = y[0] * y[0] + y[1] * y[1];
    for (int o = 16; o > 0; o >>= 1) ss += __shfl_xor_sync(~0u, ss, o);
    float sc = rsqrtf(ss + 1e-6f);
    if (!kmode) sc *= 0.125f;
#pragma unroll
    for (int e = 0; e < 2; e++) {
        int d = lane + e * 32;
        out[(size_t)t * HID + h * DK + d] = y[e] * sc;
    }
}

// ---------------- conv(K=4)+silu for v ----------------
__global__ void conv_v_kernel(const float* __restrict__ pre, const float* __restrict__ cw,
                              float* __restrict__ out) {
    int i = blockIdx.x * blockDim.x + threadIdx.x;
    if (i >= TT * VAL) return;
    int t = i >> 11, c = i & (VAL - 1);
    float acc = 0.f;
#pragma unroll
    for (int j = 0; j < CONV; j++) {
        int tt = t - (CONV - 1) + j;
        float xv = (tt >= 0) ? pre[(size_t)tt * VAL + c] : 0.f;
        acc += xv * cw[c * CONV + j];
    }
    out[i] = acc / (1.f + expf(-acc));
}

// ---------------- gated delta-rule scan ----------------
// 128 blocks (16 heads x 8 col-groups of 16), 128 threads.
// 8 lanes per column; lane 'sub' owns dims [sub*8, sub*8+8).
// Chunked (64 steps) double-buffered cp.async staging of k/q/v/beta/eg.
#define SK_OFF   0
#define SQ_OFF   8192
#define SV_OFF   16384
#define SBE_OFF  18432
#define SCAN_SMEM_F (SBE_OFF + 256)
__global__ __launch_bounds__(128) void scan_kernel(const float* __restrict__ q,
                                                   const float* __restrict__ k,
                                                   const float* __restrict__ v,
                                                   const float* __restrict__ beta,
                                                   const float* __restrict__ eg,
                                                   float* __restrict__ o) {
    extern __shared__ float ss[];
    const int h   = blockIdx.x >> 3;
    const int cg  = blockIdx.x & 7;
    const int tid = threadIdx.x;
    const int colL = tid >> 3;          // 0..15
    const int sub  = tid & 7;           // 0..7
    const int col  = cg * 16 + colL;

    float s[8];
#pragma unroll
    for (int i = 0; i < 8; i++) s[i] = 0.f;

    auto load_chunk = [&](int c0, int buf) {
#pragma unroll
        for (int i = 0; i < 8; i++) {
            int idx = tid + i * 128;
            int tl = idx >> 4, f4 = idx & 15;
            CP_ASYNC16(smaddr(&ss[SK_OFF + buf * 4096 + tl * 64 + f4 * 4]),
                       k + (size_t)(c0 + tl) * HID + h * DK + f4 * 4);
            CP_ASYNC16(smaddr(&ss[SQ_OFF + buf * 4096 + tl * 64 + f4 * 4]),
                       q + (size_t)(c0 + tl) * HID + h * DK + f4 * 4);
        }
#pragma unroll
        for (int i = 0; i < 2; i++) {
            int idx = tid + i * 128;
            int tl = idx >> 2, f4 = idx & 3;
            CP_ASYNC16(smaddr(&ss[SV_OFF + buf * 1024 + tl * 16 + f4 * 4]),
                       v + (size_t)(c0 + tl) * VAL + h * DV + cg * 16 + f4 * 4);
        }
        if (tid < 64)
            CP_ASYNC4(smaddr(&ss[SBE_OFF + buf * 128 + tid]),
                      beta + (size_t)(c0 + tid) * NH + h);
        else
            CP_ASYNC4(smaddr(&ss[SBE_OFF + buf * 128 + tid]),
                      eg + (size_t)(c0 + tid - 64) * NH + h);
    };

    load_chunk(0, 0); CP_COMMIT();

    for (int ch = 0; ch < TT / 64; ch++) {
        const int buf = ch & 1;
        if (ch + 1 < TT / 64) { load_chunk((ch + 1) * 64, buf ^ 1); CP_COMMIT(); CP_WAIT1(); }
        else CP_WAIT0();
        __syncthreads();

        const float* skb = &ss[SK_OFF + buf * 4096];
        const float* sqb = &ss[SQ_OFF + buf * 4096];
        const float* svb = &ss[SV_OFF + buf * 1024];
        const float* sbb = &ss[SBE_OFF + buf * 128];
        const int c0 = ch * 64;

        for (int tl = 0; tl < 64; tl++) {
            float bt  = sbb[tl];
            float egv = sbb[64 + tl];
            float vt  = svb[tl * 16 + colL];
            float4 k0 = *(const float4*)&skb[tl * 64 + sub * 8];
            float4 k1 = *(const float4*)&skb[tl * 64 + sub * 8 + 4];

            float p0 = s[0] * egv, p1 = s[1] * egv, p2 = s[2] * egv, p3 = s[3] * egv;
            float p4 = s[4] * egv, p5 = s[5] * egv, p6 = s[6] * egv, p7 = s[7] * egv;

            float ka = fmaf(k0.w, p3, fmaf(k0.z, p2, fmaf(k0.y, p1, k0.x * p0)));
            float kb = fmaf(k1.w, p7, fmaf(k1.z, p6, fmaf(k1.y, p5, k1.x * p4)));
            float kv = ka + kb;
            kv += __shfl_xor_sync(~0u, kv, 1);
            kv += __shfl_xor_sync(~0u, kv, 2);
            kv += __shfl_xor_sync(~0u, kv, 4);

            float vn = (vt - kv) * bt;

            s[0] = fmaf(k0.x, vn, p0); s[1] = fmaf(k0.y, vn, p1);
            s[2] = fmaf(k0.z, vn, p2); s[3] = fmaf(k0.w, vn, p3);
            s[4] = fmaf(k1.x, vn, p4); s[5] = fmaf(k1.y, vn, p5);
            s[6] = fmaf(k1.z, vn, p6); s[7] = fmaf(k1.w, vn, p7);

            float4 q0 = *(const float4*)&sqb[tl * 64 + sub * 8];
            float4 q1 = *(const float4*)&sqb[tl * 64 + sub * 8 + 4];
            float oa = fmaf(q0.w, s[3], fmaf(q0.z, s[2], fmaf(q0.y, s[1], q0.x * s[0])));
            float ob2 = fmaf(q1.w, s[7], fmaf(q1.z, s[6], fmaf(q1.y, s[5], q1.x * s[4])));
            float ov = oa + ob2;
            ov += __shfl_xor_sync(~0u, ov, 1);
            ov += __shfl_xor_sync(~0u, ov, 2);
            ov += __shfl_xor_sync(~0u, ov, 4);
            if (sub == 0) o[(size_t)(c0 + tl) * VAL + h * DV + col] = ov;
        }
        __syncthreads();
    }
}

// ---------------- gated RMSNorm on heads + silu(gate) ----------------
__global__ void gated_norm_kernel(const float* __restrict__ o, const float* __restrict__ gate,
                                  const float* __restrict__ onw, float* __restrict__ og) {
    int gw = blockIdx.x * 4 + (threadIdx.x >> 5);
    int lane = threadIdx.x & 31;
    int t = gw >> 4, h = gw & 15;
    const float* orow = o + (size_t)t * VAL + h * DV;
    float vv[4]; float ssum = 0.f;
#pragma unroll
    for (int i = 0; i < 4; i++) { vv[i] = orow[lane + i * 32]; ssum += vv[i] * vv[i]; }
    for (int off = 16; off > 0; off >>= 1) ssum += __shfl_xor_sync(~0u, ssum, off);
    float sc = rsqrtf(ssum * (1.f / DV) + 1e-5f);
#pragma unroll
    for (int i = 0; i < 4; i++) {
        int dv = lane + i * 32;
        float gt = gate[(size_t)t * VAL + h * DV + dv];
        og[(size_t)t * VAL + h * DV + dv] = vv[i] * sc * onw[dv] * (gt / (1.f + expf(-gt)));
    }
}

// ---------------- launch ----------------
extern "C" void kernel_launch(void* const* d_in, const int* in_sizes, int n_in,
                              void* d_out, int out_size) {
    const float* hs       = (const float*)d_in[0];
    const float* norm_w   = (const float*)d_in[1];
    const float* q_w      = (const float*)d_in[2];
    const float* k_w      = (const float*)d_in[3];
    const float* v_w      = (const float*)d_in[4];
    const float* a_w      = (const float*)d_in[5];
    const float* b_w      = (const float*)d_in[6];
    const float* g_w      = (const float*)d_in[7];
    const float* dt_bias  = (const float*)d_in[8];
    const float* A_log    = (const float*)d_in[9];
    const float* conv_q_w = (const float*)d_in[10];
    const float* conv_k_w = (const float*)d_in[11];
    const float* conv_v_w = (const float*)d_in[12];
    const float* o_norm_w = (const float*)d_in[13];
    const float* o_proj_w = (const float*)d_in[14];
    const float* out_proj_w = (const float*)d_in[15];
    float* out = (float*)d_out;

    float *xn, *qpre, *kpre, *vpre, *gate, *qb, *kb, *vb;
    float *beta, *eg, *ob, *og, *t1;
    cudaGetSymbolAddress((void**)&xn,   g_xn);
    cudaGetSymbolAddress((void**)&qpre, g_qpre);
    cudaGetSymbolAddress((void**)&kpre, g_kpre);
    cudaGetSymbolAddress((void**)&vpre, g_vpre);
    cudaGetSymbolAddress((void**)&gate, g_gate);
    cudaGetSymbolAddress((void**)&qb,   g_q);
    cudaGetSymbolAddress((void**)&kb,   g_k);
    cudaGetSymbolAddress((void**)&vb,   g_v);
    cudaGetSymbolAddress((void**)&beta, g_beta);
    cudaGetSymbolAddress((void**)&eg,   g_eg);
    cudaGetSymbolAddress((void**)&ob,   g_o);
    cudaGetSymbolAddress((void**)&og,   g_og);
    cudaGetSymbolAddress((void**)&t1,   g_t1);

    static bool attr_set = false;
    if (!attr_set) {
        cudaFuncSetAttribute(tf32_gemm, cudaFuncAttributeMaxDynamicSharedMemorySize, GEMM_SMEM_BYTES);
        cudaFuncSetAttribute(qkvg_gemm, cudaFuncAttributeMaxDynamicSharedMemorySize, GEMM_SMEM_BYTES);
        cudaFuncSetAttribute(scan_kernel, cudaFuncAttributeMaxDynamicSharedMemorySize, SCAN_SMEM_F * 4);
        attr_set = true;
    }

    rmsnorm_kernel<<<TT, 256>>>(hs, norm_w, xn);

    qkvg_gemm<<<dim3(48, TT / 128), 256, GEMM_SMEM_BYTES>>>(xn, q_w, k_w, v_w, g_w,
                                                            qpre, kpre, vpre, gate);
    proj_ab_kernel<<<(TT * NH) / 8, 256>>>(xn, a_w, b_w, dt_bias, A_log, beta, eg);

    conv_qk_kernel<<<(TT * NH) / 4, 128>>>(qpre, conv_q_w, qb, 0);
    conv_qk_kernel<<<(TT * NH) / 4, 128>>>(kpre, conv_k_w, kb, 1);
    conv_v_kernel<<<(TT * VAL) / 256, 256>>>(vpre, conv_v_w, vb);

    scan_kernel<<<128, 128, SCAN_SMEM_F * 4>>>(qb, kb, vb, beta, eg, ob);

    gated_norm_kernel<<<(TT * NH) / 4, 128>>>(ob, gate, o_norm_w, og);

    tf32_gemm<<<dim3(HID / 128, TT / 128), 256, GEMM_SMEM_BYTES>>>(og, o_proj_w, t1, HID, VAL);
    tf32_gemm<<<dim3(HID / 128, TT / 128), 256, GEMM_SMEM_BYTES>>>(t1, out_proj_w, out, HID, HID);
}

// round 7
// speedup vs baseline: 2.8637x; 1.3522x over previous
#include <cuda_runtime.h>
#include <cuda_fp16.h>
#include <math.h>
#include <stdint.h>

// ---------------- problem constants ----------------
#define TT   2048
#define HID  1024
#define NH   16
#define DK   64
#define DV   128
#define VAL  2048   // NH*DV
#define CONV 4

// ---------------- scratch ----------------
__device__ __align__(16) float  g_xn  [TT * HID];
__device__ __align__(16) float  g_qpre[TT * HID];
__device__ __align__(16) float  g_kpre[TT * HID];
__device__ __align__(16) float  g_vpre[TT * VAL];
__device__ __align__(16) float  g_gate[TT * VAL];
__device__ __align__(16) float  g_q   [TT * HID];
__device__ __align__(16) float  g_k   [TT * HID];
__device__ __align__(16) float  g_v   [TT * VAL];
__device__ __align__(16) float  g_beta[TT * NH];
__device__ __align__(16) float  g_eg  [TT * NH];
__device__ __align__(16) float  g_o   [TT * VAL];

// fp16 operands
__device__ __align__(16) __half g_xn16 [TT * HID];
__device__ __align__(16) __half g_og16 [TT * VAL];
__device__ __align__(16) __half g_t116 [TT * HID];
__device__ __align__(16) __half g_qw16 [HID * HID];
__device__ __align__(16) __half g_kw16 [HID * HID];
__device__ __align__(16) __half g_vw16 [VAL * HID];
__device__ __align__(16) __half g_gw16 [VAL * HID];
__device__ __align__(16) __half g_opw16[HID * VAL];
__device__ __align__(16) __half g_ow16 [HID * HID];

// ---------------- helpers ----------------
__device__ __forceinline__ uint32_t smaddr(const void* p) {
    return (uint32_t)__cvta_generic_to_shared(p);
}
#define CP_ASYNC16(dst, src) \
    asm volatile("cp.async.cg.shared.global [%0], [%1], 16;" :: "r"(dst), "l"(src))
#define CP_ASYNC4(dst, src) \
    asm volatile("cp.async.ca.shared.global [%0], [%1], 4;" :: "r"(dst), "l"(src))
#define CP_COMMIT() asm volatile("cp.async.commit_group;")
#define CP_WAIT2()  asm volatile("cp.async.wait_group 2;")
#define CP_WAIT1()  asm volatile("cp.async.wait_group 1;")
#define CP_WAIT0()  asm volatile("cp.async.wait_group 0;")

// ---------------- weight f32 -> f16 conversion (all 6 weight matrices) ----------------
// in float4 units: q 262144 | k 262144 | v 524288 | g 524288 | op 524288 | out 262144
#define CW_TOTAL4 2359296
__global__ void convert_w_kernel(const float* __restrict__ qw, const float* __restrict__ kw,
                                 const float* __restrict__ vw, const float* __restrict__ gw,
                                 const float* __restrict__ opw, const float* __restrict__ ow) {
    int gid = blockIdx.x * 256 + threadIdx.x;
    if (gid >= CW_TOTAL4) return;
    const float* s; __half* d; int o;
    if      (gid < 262144)  { s = qw;  d = g_qw16;  o = gid; }
    else if (gid < 524288)  { s = kw;  d = g_kw16;  o = gid - 262144; }
    else if (gid < 1048576) { s = vw;  d = g_vw16;  o = gid - 524288; }
    else if (gid < 1572864) { s = gw;  d = g_gw16;  o = gid - 1048576; }
    else if (gid < 2097152) { s = opw; d = g_opw16; o = gid - 1572864; }
    else                    { s = ow;  d = g_ow16;  o = gid - 2097152; }
    float4 v = ((const float4*)s)[o];
    ((__half2*)d)[o * 2]     = __floats2half2_rn(v.x, v.y);
    ((__half2*)d)[o * 2 + 1] = __floats2half2_rn(v.z, v.w);
}

// ---------------- RMSNorm (writes f32 + f16) ----------------
__global__ void rmsnorm_kernel(const float* __restrict__ x, const float* __restrict__ w,
                               float* __restrict__ y, __half* __restrict__ y16) {
    int row = blockIdx.x;
    int tid = threadIdx.x;                     // 256, 4 consecutive floats each
    float4 v = ((const float4*)(x + (size_t)row * HID))[tid];
    float s = v.x * v.x + v.y * v.y + v.z * v.z + v.w * v.w;
    __shared__ float red[256];
    red[tid] = s; __syncthreads();
    for (int o = 128; o > 0; o >>= 1) { if (tid < o) red[tid] += red[tid + o]; __syncthreads(); }
    float scale = rsqrtf(red[0] * (1.f / HID) + 1e-6f);
    float4 wv = ((const float4*)w)[tid];
    float4 out;
    out.x = v.x * scale * wv.x; out.y = v.y * scale * wv.y;
    out.z = v.z * scale * wv.z; out.w = v.w * scale * wv.w;
    ((float4*)(y + (size_t)row * HID))[tid] = out;
    __half2* y2 = (__half2*)(y16 + (size_t)row * HID);
    y2[tid * 2]     = __floats2half2_rn(out.x, out.y);
    y2[tid * 2 + 1] = __floats2half2_rn(out.z, out.w);
}

// ---------------- fp16 tensor-core GEMM body: C = A[M,K] @ W[N,K]^T ----------------
// 128x128x32 tiles, 256 threads (8 warps 2x4), warp tile 64x32, mma m16n8k16,
// 4-stage cp.async. Smem in fragment-register order (uint32 = 2 f16 along k):
//   A: [mf(8)][ks(2)][reg(4)][lane(32)]   B: [nf(16)][ks(2)][reg(2)][lane(32)]
#define STAGE_U32 4096     // 2048 A + 2048 B
#define GEMM16_SMEM_BYTES (4 * STAGE_U32 * 4)

template<bool HALF_OUT>
__device__ __forceinline__ void gemm16_body(const __half* __restrict__ A,
                                            const __half* __restrict__ W,
                                            void* __restrict__ Cv,
                                            int N, int K, int bm, int bn,
                                            uint32_t* su) {
    const int tid  = threadIdx.x;
    const int lane = tid & 31;
    const int warp = tid >> 5;
    const int wm   = warp & 1;
    const int wn   = warp >> 1;

    float acc[4][4][4];
#pragma unroll
    for (int i = 0; i < 4; i++)
#pragma unroll
        for (int j = 0; j < 4; j++)
#pragma unroll
            for (int r = 0; r < 4; r++) acc[i][j][r] = 0.f;

    uint32_t sbase = smaddr(su);
    int m_[2], q_[2];
#pragma unroll
    for (int p = 0; p < 2; p++) { int idx = tid + p * 256; m_[p] = idx >> 2; q_[p] = idx & 3; }

    auto load_tile = [&](int t, int stage) {
        uint32_t sb = sbase + (uint32_t)stage * STAGE_U32 * 4;
#pragma unroll
        for (int p = 0; p < 2; p++) {
            int m = m_[p], q = q_[p];
            int mf = m >> 4, mr = m & 15, ks = q >> 1;
            int regA = (mr >> 3) + ((q & 1) << 1);
            uint32_t dA = sb + (uint32_t)((((mf * 2 + ks) * 4 + regA) * 32 + (mr & 7) * 4)) * 4u;
            CP_ASYNC16(dA, A + (size_t)(bm + m) * K + t * 32 + q * 8);
            int nf = m >> 3, nr = m & 7;
            int regB = q & 1;
            uint32_t dB = sb + (uint32_t)(2048 + (((nf * 2 + ks) * 2 + regB) * 32 + nr * 4)) * 4u;
            CP_ASYNC16(dB, W + (size_t)(bn + m) * K + t * 32 + q * 8);
        }
    };

    const int NT = K >> 5;
    load_tile(0, 0); CP_COMMIT();
    load_tile(1, 1); CP_COMMIT();
    load_tile(2, 2); CP_COMMIT();

    for (int t = 0; t < NT; t++) {
        CP_WAIT2();
        __syncthreads();
        if (t + 3 < NT) load_tile(t + 3, (t + 3) & 3);
        CP_COMMIT();                     // empty group near tail keeps counts uniform

        const uint32_t* Ab = su + (t & 3) * STAGE_U32;
        const uint32_t* Bb = Ab + 2048;
#pragma unroll
        for (int ks = 0; ks < 2; ks++) {
            uint32_t a[4][4], b[4][2];
#pragma unroll
            for (int mf = 0; mf < 4; mf++) {
                int base = (((wm * 4 + mf) * 2 + ks) * 4) * 32 + lane;
#pragma unroll
                for (int r = 0; r < 4; r++) a[mf][r] = Ab[base + r * 32];
            }
#pragma unroll
            for (int nf = 0; nf < 4; nf++) {
                int base = (((wn * 4 + nf) * 2 + ks) * 2) * 32 + lane;
#pragma unroll
                for (int r = 0; r < 2; r++) b[nf][r] = Bb[base + r * 32];
            }
#pragma unroll
            for (int mf = 0; mf < 4; mf++)
#pragma unroll
                for (int nf = 0; nf < 4; nf++) {
                    asm volatile(
                        "mma.sync.aligned.m16n8k16.row.col.f32.f16.f16.f32 "
                        "{%0,%1,%2,%3}, {%4,%5,%6,%7}, {%8,%9}, {%0,%1,%2,%3};"
                        : "+f"(acc[mf][nf][0]), "+f"(acc[mf][nf][1]),
                          "+f"(acc[mf][nf][2]), "+f"(acc[mf][nf][3])
                        : "r"(a[mf][0]), "r"(a[mf][1]), "r"(a[mf][2]), "r"(a[mf][3]),
                          "r"(b[nf][0]), "r"(b[nf][1]));
                }
        }
    }

    const int row0 = bm + wm * 64 + (lane >> 2);
    const int col0 = bn + wn * 32 + (lane & 3) * 2;
#pragma unroll
    for (int mf = 0; mf < 4; mf++)
#pragma unroll
        for (int nf = 0; nf < 4; nf++) {
            int r = row0 + mf * 16;
            int c = col0 + nf * 8;
            if (HALF_OUT) {
                __half* C = (__half*)Cv;
                *(__half2*)(C + (size_t)r * N + c)       = __floats2half2_rn(acc[mf][nf][0], acc[mf][nf][1]);
                *(__half2*)(C + (size_t)(r + 8) * N + c) = __floats2half2_rn(acc[mf][nf][2], acc[mf][nf][3]);
            } else {
                float* C = (float*)Cv;
                *(float2*)(C + (size_t)r * N + c)       = make_float2(acc[mf][nf][0], acc[mf][nf][1]);
                *(float2*)(C + (size_t)(r + 8) * N + c) = make_float2(acc[mf][nf][2], acc[mf][nf][3]);
            }
        }
}

// fused q/k/v/g projection: 48 N-tiles (q:0-7, k:8-15, v:16-31, g:32-47)
__global__ __launch_bounds__(256) void qkvg_gemm16(const __half* __restrict__ xn16,
                                                   float* __restrict__ qo, float* __restrict__ ko,
                                                   float* __restrict__ vo, float* __restrict__ go) {
    extern __shared__ uint32_t su[];
    int nt = blockIdx.x;
    const __half* W; float* C; int N, bn;
    if (nt < 8)       { W = g_qw16; C = qo; N = HID; bn = nt << 7; }
    else if (nt < 16) { W = g_kw16; C = ko; N = HID; bn = (nt - 8) << 7; }
    else if (nt < 32) { W = g_vw16; C = vo; N = VAL; bn = (nt - 16) << 7; }
    else              { W = g_gw16; C = go; N = VAL; bn = (nt - 32) << 7; }
    gemm16_body<false>(xn16, W, C, N, HID, blockIdx.y * 128, bn, su);
}

__global__ __launch_bounds__(256) void gemm16_h(const __half* __restrict__ A,
                                                const __half* __restrict__ W,
                                                __half* __restrict__ C, int N, int K) {
    extern __shared__ uint32_t su[];
    gemm16_body<true>(A, W, C, N, K, blockIdx.y * 128, blockIdx.x * 128, su);
}
__global__ __launch_bounds__(256) void gemm16_f(const __half* __restrict__ A,
                                                const __half* __restrict__ W,
                                                float* __restrict__ C, int N, int K) {
    extern __shared__ uint32_t su[];
    gemm16_body<false>(A, W, C, N, K, blockIdx.y * 128, blockIdx.x * 128, su);
}

// ---------------- fused a/b thin projections + gate scalars ----------------
__global__ void proj_ab_kernel(const float* __restrict__ X,
                               const float* __restrict__ a_w, const float* __restrict__ b_w,
                               const float* __restrict__ dt_bias, const float* __restrict__ A_log,
                               float* __restrict__ beta, float* __restrict__ eg) {
    int gw = blockIdx.x * 8 + (threadIdx.x >> 5);
    int lane = threadIdx.x & 31;
    int m = gw >> 4, h = gw & 15;
    const float4* xr = (const float4*)(X + (size_t)m * HID);
    const float4* ar = (const float4*)(a_w + (size_t)h * HID);
    const float4* br = (const float4*)(b_w + (size_t)h * HID);
    float sa = 0.f, sb = 0.f;
#pragma unroll
    for (int i = 0; i < 8; i++) {
        float4 x4 = xr[lane + i * 32];
        float4 a4 = ar[lane + i * 32];
        float4 b4 = br[lane + i * 32];
        sa += x4.x * a4.x + x4.y * a4.y + x4.z * a4.z + x4.w * a4.w;
        sb += x4.x * b4.x + x4.y * b4.y + x4.z * b4.z + x4.w * b4.w;
    }
    for (int o = 16; o > 0; o >>= 1) {
        sa += __shfl_xor_sync(~0u, sa, o);
        sb += __shfl_xor_sync(~0u, sb, o);
    }
    if (lane == 0) {
        beta[m * NH + h] = 1.f / (1.f + expf(-sb));
        float xv = sa + dt_bias[h];
        float sp = (xv > 20.f) ? xv : log1pf(expf(xv));
        eg[m * NH + h] = expf(-expf(A_log[h]) * sp);
    }
}

// ---------------- conv(K=4)+silu + per-head postproc for q and k (one launch) ----------------
__global__ void conv_qk2_kernel(const float* __restrict__ qpre, const float* __restrict__ kpre,
                                const float* __restrict__ cwq, const float* __restrict__ cwk,
                                float* __restrict__ qout, float* __restrict__ kout) {
    const int kmode = blockIdx.y;
    const float* pre = kmode ? kpre : qpre;
    const float* cw  = kmode ? cwk : cwq;
    float* out       = kmode ? kout : qout;
    int gw = blockIdx.x * 4 + (threadIdx.x >> 5);
    int lane = threadIdx.x & 31;
    int t = gw >> 4, h = gw & 15;
    float y[2];
#pragma unroll
    for (int e = 0; e < 2; e++) {
        int d = lane + e * 32;
        int c = h * DK + d;
        float acc = 0.f;
#pragma unroll
        for (int i = 0; i < CONV; i++) {
            int tt = t - (CONV - 1) + i;
            float xv = (tt >= 0) ? pre[(size_t)tt * HID + c] : 0.f;
            acc += xv * cw[c * CONV + i];
        }
        y[e] = acc / (1.f + expf(-acc));
    }
    if (kmode) {
        float m = y[0] + y[1];
        for (int o = 16; o > 0; o >>= 1) m += __shfl_xor_sync(~0u, m, o);
        m *= (1.f / DK);
        y[0] -= m; y[1] -= m;
    }
    float ss = y[0] * y[0] + y[1] * y[1];
    for (int o = 16; o > 0; o >>= 1) ss += __shfl_xor_sync(~0u, ss, o);
    float sc = rsqrtf(ss + 1e-6f);
    if (!kmode) sc *= 0.125f;
#pragma unroll
    for (int e = 0; e < 2; e++) {
        int d = lane + e * 32;
        out[(size_t)t * HID + h * DK + d] = y[e] * sc;
    }
}

// ---------------- conv(K=4)+silu for v ----------------
__global__ void conv_v_kernel(const float* __restrict__ pre, const float* __restrict__ cw,
                              float* __restrict__ out) {
    int i = blockIdx.x * blockDim.x + threadIdx.x;
    if (i >= TT * VAL) return;
    int t = i >> 11, c = i & (VAL - 1);
    float acc = 0.f;
#pragma unroll
    for (int j = 0; j < CONV; j++) {
        int tt = t - (CONV - 1) + j;
        float xv = (tt >= 0) ? pre[(size_t)tt * VAL + c] : 0.f;
        acc += xv * cw[c * CONV + j];
    }
    out[i] = acc / (1.f + expf(-acc));
}

// ---------------- gated delta-rule scan ----------------
#define SK_OFF   0
#define SQ_OFF   8192
#define SV_OFF   16384
#define SBE_OFF  18432
#define SCAN_SMEM_F (SBE_OFF + 256)
__global__ __launch_bounds__(128) void scan_kernel(const float* __restrict__ q,
                                                   const float* __restrict__ k,
                                                   const float* __restrict__ v,
                                                   const float* __restrict__ beta,
                                                   const float* __restrict__ eg,
                                                   float* __restrict__ o) {
    extern __shared__ float ss[];
    const int h   = blockIdx.x >> 3;
    const int cg  = blockIdx.x & 7;
    const int tid = threadIdx.x;
    const int colL = tid >> 3;
    const int sub  = tid & 7;
    const int col  = cg * 16 + colL;

    float s[8];
#pragma unroll
    for (int i = 0; i < 8; i++) s[i] = 0.f;

    auto load_chunk = [&](int c0, int buf) {
#pragma unroll
        for (int i = 0; i < 8; i++) {
            int idx = tid + i * 128;
            int tl = idx >> 4, f4 = idx & 15;
            CP_ASYNC16(smaddr(&ss[SK_OFF + buf * 4096 + tl * 64 + f4 * 4]),
                       k + (size_t)(c0 + tl) * HID + h * DK + f4 * 4);
            CP_ASYNC16(smaddr(&ss[SQ_OFF + buf * 4096 + tl * 64 + f4 * 4]),
                       q + (size_t)(c0 + tl) * HID + h * DK + f4 * 4);
        }
#pragma unroll
        for (int i = 0; i < 2; i++) {
            int idx = tid + i * 128;
            int tl = idx >> 2, f4 = idx & 3;
            CP_ASYNC16(smaddr(&ss[SV_OFF + buf * 1024 + tl * 16 + f4 * 4]),
                       v + (size_t)(c0 + tl) * VAL + h * DV + cg * 16 + f4 * 4);
        }
        if (tid < 64)
            CP_ASYNC4(smaddr(&ss[SBE_OFF + buf * 128 + tid]),
                      beta + (size_t)(c0 + tid) * NH + h);
        else
            CP_ASYNC4(smaddr(&ss[SBE_OFF + buf * 128 + tid]),
                      eg + (size_t)(c0 + tid - 64) * NH + h);
    };

    load_chunk(0, 0); CP_COMMIT();

    for (int ch = 0; ch < TT / 64; ch++) {
        const int buf = ch & 1;
        if (ch + 1 < TT / 64) { load_chunk((ch + 1) * 64, buf ^ 1); CP_COMMIT(); CP_WAIT1(); }
        else CP_WAIT0();
        __syncthreads();

        const float* skb = &ss[SK_OFF + buf * 4096];
        const float* sqb = &ss[SQ_OFF + buf * 4096];
        const float* svb = &ss[SV_OFF + buf * 1024];
        const float* sbb = &ss[SBE_OFF + buf * 128];
        const int c0 = ch * 64;

        for (int tl = 0; tl < 64; tl++) {
            float bt  = sbb[tl];
            float egv = sbb[64 + tl];
            float vt  = svb[tl * 16 + colL];
            float4 k0 = *(const float4*)&skb[tl * 64 + sub * 8];
            float4 k1 = *(const float4*)&skb[tl * 64 + sub * 8 + 4];

            float p0 = s[0] * egv, p1 = s[1] * egv, p2 = s[2] * egv, p3 = s[3] * egv;
            float p4 = s[4] * egv, p5 = s[5] * egv, p6 = s[6] * egv, p7 = s[7] * egv;

            float ka = fmaf(k0.w, p3, fmaf(k0.z, p2, fmaf(k0.y, p1, k0.x * p0)));
            float kb = fmaf(k1.w, p7, fmaf(k1.z, p6, fmaf(k1.y, p5, k1.x * p4)));
            float kv = ka + kb;
            kv += __shfl_xor_sync(~0u, kv, 1);
            kv += __shfl_xor_sync(~0u, kv, 2);
            kv += __shfl_xor_sync(~0u, kv, 4);

            float vn = (vt - kv) * bt;

            s[0] = fmaf(k0.x, vn, p0); s[1] = fmaf(k0.y, vn, p1);
            s[2] = fmaf(k0.z, vn, p2); s[3] = fmaf(k0.w, vn, p3);
            s[4] = fmaf(k1.x, vn, p4); s[5] = fmaf(k1.y, vn, p5);
            s[6] = fmaf(k1.z, vn, p6); s[7] = fmaf(k1.w, vn, p7);

            float4 q0 = *(const float4*)&sqb[tl * 64 + sub * 8];
            float4 q1 = *(const float4*)&sqb[tl * 64 + sub * 8 + 4];
            float oa  = fmaf(q0.w, s[3], fmaf(q0.z, s[2], fmaf(q0.y, s[1], q0.x * s[0])));
            float ob2 = fmaf(q1.w, s[7], fmaf(q1.z, s[6], fmaf(q1.y, s[5], q1.x * s[4])));
            float ov = oa + ob2;
            ov += __shfl_xor_sync(~0u, ov, 1);
            ov += __shfl_xor_sync(~0u, ov, 2);
            ov += __shfl_xor_sync(~0u, ov, 4);
            if (sub == 0) o[(size_t)(c0 + tl) * VAL + h * DV + col] = ov;
        }
        __syncthreads();
    }
}

// ---------------- gated RMSNorm on heads + silu(gate) -> f16 ----------------
__global__ void gated_norm_kernel(const float* __restrict__ o, const float* __restrict__ gate,
                                  const float* __restrict__ onw, __half* __restrict__ og16) {
    int gw = blockIdx.x * 4 + (threadIdx.x >> 5);
    int lane = threadIdx.x & 31;
    int t = gw >> 4, h = gw & 15;
    const float* orow = o + (size_t)t * VAL + h * DV;
    float4 vv = ((const float4*)orow)[lane];                 // 32 lanes x 4 = 128
    float ssum = vv.x * vv.x + vv.y * vv.y + vv.z * vv.z + vv.w * vv.w;
    for (int off = 16; off > 0; off >>= 1) ssum += __shfl_xor_sync(~0u, ssum, off);
    float sc = rsqrtf(ssum * (1.f / DV) + 1e-5f);
    float4 gt = ((const float4*)(gate + (size_t)t * VAL + h * DV))[lane];
    float4 wn = ((const float4*)onw)[lane];
    float o0 = vv.x * sc * wn.x * (gt.x / (1.f + expf(-gt.x)));
    float o1 = vv.y * sc * wn.y * (gt.y / (1.f + expf(-gt.y)));
    float o2 = vv.z * sc * wn.z * (gt.z / (1.f + expf(-gt.z)));
    float o3 = vv.w * sc * wn.w * (gt.w / (1.f + expf(-gt.w)));
    __half2* og2 = (__half2*)(og16 + (size_t)t * VAL + h * DV);
    og2[lane * 2]     = __floats2half2_rn(o0, o1);
    og2[lane * 2 + 1] = __floats2half2_rn(o2, o3);
}

// ---------------- launch ----------------
extern "C" void kernel_launch(void* const* d_in, const int* in_sizes, int n_in,
                              void* d_out, int out_size) {
    const float* hs       = (const float*)d_in[0];
    const float* norm_w   = (const float*)d_in[1];
    const float* q_w      = (const float*)d_in[2];
    const float* k_w      = (const float*)d_in[3];
    const float* v_w      = (const float*)d_in[4];
    const float* a_w      = (const float*)d_in[5];
    const float* b_w      = (const float*)d_in[6];
    const float* g_w      = (const float*)d_in[7];
    const float* dt_bias  = (const float*)d_in[8];
    const float* A_log    = (const float*)d_in[9];
    const float* conv_q_w = (const float*)d_in[10];
    const float* conv_k_w = (const float*)d_in[11];
    const float* conv_v_w = (const float*)d_in[12];
    const float* o_norm_w = (const float*)d_in[13];
    const float* o_proj_w = (const float*)d_in[14];
    const float* out_proj_w = (const float*)d_in[15];
    float* out = (float*)d_out;

    float *xn, *qpre, *kpre, *vpre, *gate, *qb, *kb, *vb, *beta, *eg, *ob;
    __half *xn16, *og16, *t116, *opw16, *ow16;
    cudaGetSymbolAddress((void**)&xn,   g_xn);
    cudaGetSymbolAddress((void**)&qpre, g_qpre);
    cudaGetSymbolAddress((void**)&kpre, g_kpre);
    cudaGetSymbolAddress((void**)&vpre, g_vpre);
    cudaGetSymbolAddress((void**)&gate, g_gate);
    cudaGetSymbolAddress((void**)&qb,   g_q);
    cudaGetSymbolAddress((void**)&kb,   g_k);
    cudaGetSymbolAddress((void**)&vb,   g_v);
    cudaGetSymbolAddress((void**)&beta, g_beta);
    cudaGetSymbolAddress((void**)&eg,   g_eg);
    cudaGetSymbolAddress((void**)&ob,   g_o);
    cudaGetSymbolAddress((void**)&xn16, g_xn16);
    cudaGetSymbolAddress((void**)&og16, g_og16);
    cudaGetSymbolAddress((void**)&t116, g_t116);
    cudaGetSymbolAddress((void**)&opw16, g_opw16);
    cudaGetSymbolAddress((void**)&ow16,  g_ow16);

    static bool attr_set = false;
    if (!attr_set) {
        cudaFuncSetAttribute(qkvg_gemm16, cudaFuncAttributeMaxDynamicSharedMemorySize, GEMM16_SMEM_BYTES);
        cudaFuncSetAttribute(gemm16_h,    cudaFuncAttributeMaxDynamicSharedMemorySize, GEMM16_SMEM_BYTES);
        cudaFuncSetAttribute(gemm16_f,    cudaFuncAttributeMaxDynamicSharedMemorySize, GEMM16_SMEM_BYTES);
        cudaFuncSetAttribute(scan_kernel, cudaFuncAttributeMaxDynamicSharedMemorySize, SCAN_SMEM_F * 4);
        attr_set = true;
    }

    convert_w_kernel<<<(CW_TOTAL4 + 255) / 256, 256>>>(q_w, k_w, v_w, g_w, o_proj_w, out_proj_w);
    rmsnorm_kernel<<<TT, 256>>>(hs, norm_w, xn, xn16);

    qkvg_gemm16<<<dim3(48, TT / 128), 256, GEMM16_SMEM_BYTES>>>(xn16, qpre, kpre, vpre, gate);
    proj_ab_kernel<<<(TT * NH) / 8, 256>>>(xn, a_w, b_w, dt_bias, A_log, beta, eg);

    conv_qk2_kernel<<<dim3((TT * NH) / 4, 2), 128>>>(qpre, kpre, conv_q_w, conv_k_w, qb, kb);
    conv_v_kernel<<<(TT * VAL) / 256, 256>>>(vpre, conv_v_w, vb);

    scan_kernel<<<128, 128, SCAN_SMEM_F * 4>>>(qb, kb, vb, beta, eg, ob);

    gated_norm_kernel<<<(TT * NH) / 4, 128>>>(ob, gate, o_norm_w, og16);

    gemm16_h<<<dim3(HID / 128, TT / 128), 256, GEMM16_SMEM_BYTES>>>(og16, opw16, t116, HID, VAL);
    gemm16_f<<<dim3(HID / 128, TT / 128), 256, GEMM16_SMEM_BYTES>>>(t116, ow16, out, HID, HID);
}

// round 15
// speedup vs baseline: 2.9406x; 1.0268x over previous
#include <cuda_runtime.h>
#include <cuda_fp16.h>
#include <math.h>
#include <stdint.h>

// ---------------- problem constants ----------------
#define TT   2048
#define HID  1024
#define NH   16
#define DK   64
#define DV   128
#define VAL  2048   // NH*DV
#define CONV 4

// ---------------- scratch ----------------
__device__ __align__(16) float  g_xn  [TT * HID];
__device__ __align__(16) float  g_qpre[TT * HID];
__device__ __align__(16) float  g_kpre[TT * HID];
__device__ __align__(16) float  g_vpre[TT * VAL];
__device__ __align__(16) float  g_gate[TT * VAL];
__device__ __align__(16) float  g_q   [TT * HID];
__device__ __align__(16) float  g_k   [TT * HID];
__device__ __align__(16) float  g_v   [TT * VAL];
__device__ __align__(16) float  g_beta[TT * NH];
__device__ __align__(16) float  g_eg  [TT * NH];
__device__ __align__(16) float  g_o   [TT * VAL];

// fp16 operands
__device__ __align__(16) __half g_xn16 [TT * HID];
__device__ __align__(16) __half g_og16 [TT * VAL];
__device__ __align__(16) __half g_t116 [TT * HID];
__device__ __align__(16) __half g_qw16 [HID * HID];
__device__ __align__(16) __half g_kw16 [HID * HID];
__device__ __align__(16) __half g_vw16 [VAL * HID];
__device__ __align__(16) __half g_gw16 [VAL * HID];
__device__ __align__(16) __half g_opw16[HID * VAL];
__device__ __align__(16) __half g_ow16 [HID * HID];

// ---------------- helpers ----------------
__device__ __forceinline__ uint32_t smaddr(const void* p) {
    return (uint32_t)__cvta_generic_to_shared(p);
}
#define CP_ASYNC16(dst, src) \
    asm volatile("cp.async.cg.shared.global [%0], [%1], 16;" :: "r"(dst), "l"(src))
#define CP_ASYNC4(dst, src) \
    asm volatile("cp.async.ca.shared.global [%0], [%1], 4;" :: "r"(dst), "l"(src))
#define CP_COMMIT() asm volatile("cp.async.commit_group;")
#define CP_WAIT2()  asm volatile("cp.async.wait_group 2;")
#define CP_WAIT1()  asm volatile("cp.async.wait_group 1;")
#define CP_WAIT0()  asm volatile("cp.async.wait_group 0;")

// ---------------- weight f32 -> f16 conversion ----------------
#define CW_TOTAL4 2359296
__global__ void convert_w_kernel(const float* __restrict__ qw, const float* __restrict__ kw,
                                 const float* __restrict__ vw, const float* __restrict__ gw,
                                 const float* __restrict__ opw, const float* __restrict__ ow) {
    int gid = blockIdx.x * 256 + threadIdx.x;
    if (gid >= CW_TOTAL4) return;
    const float* s; __half* d; int o;
    if      (gid < 262144)  { s = qw;  d = g_qw16;  o = gid; }
    else if (gid < 524288)  { s = kw;  d = g_kw16;  o = gid - 262144; }
    else if (gid < 1048576) { s = vw;  d = g_vw16;  o = gid - 524288; }
    else if (gid < 1572864) { s = gw;  d = g_gw16;  o = gid - 1048576; }
    else if (gid < 2097152) { s = opw; d = g_opw16; o = gid - 1572864; }
    else                    { s = ow;  d = g_ow16;  o = gid - 2097152; }
    float4 v = ((const float4*)s)[o];
    ((__half2*)d)[o * 2]     = __floats2half2_rn(v.x, v.y);
    ((__half2*)d)[o * 2 + 1] = __floats2half2_rn(v.z, v.w);
}

// ---------------- RMSNorm (writes f32 + f16) ----------------
__global__ void rmsnorm_kernel(const float* __restrict__ x, const float* __restrict__ w,
                               float* __restrict__ y, __half* __restrict__ y16) {
    int row = blockIdx.x;
    int tid = threadIdx.x;
    float4 v = ((const float4*)(x + (size_t)row * HID))[tid];
    float s = v.x * v.x + v.y * v.y + v.z * v.z + v.w * v.w;
    __shared__ float red[256];
    red[tid] = s; __syncthreads();
    for (int o = 128; o > 0; o >>= 1) { if (tid < o) red[tid] += red[tid + o]; __syncthreads(); }
    float scale = rsqrtf(red[0] * (1.f / HID) + 1e-6f);
    float4 wv = ((const float4*)w)[tid];
    float4 out;
    out.x = v.x * scale * wv.x; out.y = v.y * scale * wv.y;
    out.z = v.z * scale * wv.z; out.w = v.w * scale * wv.w;
    ((float4*)(y + (size_t)row * HID))[tid] = out;
    __half2* y2 = (__half2*)(y16 + (size_t)row * HID);
    y2[tid * 2]     = __floats2half2_rn(out.x, out.y);
    y2[tid * 2 + 1] = __floats2half2_rn(out.z, out.w);
}

// ---------------- fp16 tensor-core GEMM body ----------------
#define STAGE_U32 4096
#define GEMM16_SMEM_BYTES (4 * STAGE_U32 * 4)

template<bool HALF_OUT>
__device__ __forceinline__ void gemm16_body(const __half* __restrict__ A,
                                            const __half* __restrict__ W,
                                            void* __restrict__ Cv,
                                            int N, int K, int bm, int bn,
                                            uint32_t* su) {
    const int tid  = threadIdx.x;
    const int lane = tid & 31;
    const int warp = tid >> 5;
    const int wm   = warp & 1;
    const int wn   = warp >> 1;

    float acc[4][4][4];
#pragma unroll
    for (int i = 0; i < 4; i++)
#pragma unroll
        for (int j = 0; j < 4; j++)
#pragma unroll
            for (int r = 0; r < 4; r++) acc[i][j][r] = 0.f;

    uint32_t sbase = smaddr(su);
    int m_[2], q_[2];
#pragma unroll
    for (int p = 0; p < 2; p++) { int idx = tid + p * 256; m_[p] = idx >> 2; q_[p] = idx & 3; }

    auto load_tile = [&](int t, int stage) {
        uint32_t sb = sbase + (uint32_t)stage * STAGE_U32 * 4;
#pragma unroll
        for (int p = 0; p < 2; p++) {
            int m = m_[p], q = q_[p];
            int mf = m >> 4, mr = m & 15, ks = q >> 1;
            int regA = (mr >> 3) + ((q & 1) << 1);
            uint32_t dA = sb + (uint32_t)((((mf * 2 + ks) * 4 + regA) * 32 + (mr & 7) * 4)) * 4u;
            CP_ASYNC16(dA, A + (size_t)(bm + m) * K + t * 32 + q * 8);
            int nf = m >> 3, nr = m & 7;
            int regB = q & 1;
            uint32_t dB = sb + (uint32_t)(2048 + (((nf * 2 + ks) * 2 + regB) * 32 + nr * 4)) * 4u;
            CP_ASYNC16(dB, W + (size_t)(bn + m) * K + t * 32 + q * 8);
        }
    };

    const int NT = K >> 5;
    load_tile(0, 0); CP_COMMIT();
    load_tile(1, 1); CP_COMMIT();
    load_tile(2, 2); CP_COMMIT();

    for (int t = 0; t < NT; t++) {
        CP_WAIT2();
        __syncthreads();
        if (t + 3 < NT) load_tile(t + 3, (t + 3) & 3);
        CP_COMMIT();

        const uint32_t* Ab = su + (t & 3) * STAGE_U32;
        const uint32_t* Bb = Ab + 2048;
#pragma unroll
        for (int ks = 0; ks < 2; ks++) {
            uint32_t a[4][4], b[4][2];
#pragma unroll
            for (int mf = 0; mf < 4; mf++) {
                int base = (((wm * 4 + mf) * 2 + ks) * 4) * 32 + lane;
#pragma unroll
                for (int r = 0; r < 4; r++) a[mf][r] = Ab[base + r * 32];
            }
#pragma unroll
            for (int nf = 0; nf < 4; nf++) {
                int base = (((wn * 4 + nf) * 2 + ks) * 2) * 32 + lane;
#pragma unroll
                for (int r = 0; r < 2; r++) b[nf][r] = Bb[base + r * 32];
            }
#pragma unroll
            for (int mf = 0; mf < 4; mf++)
#pragma unroll
                for (int nf = 0; nf < 4; nf++) {
                    asm volatile(
                        "mma.sync.aligned.m16n8k16.row.col.f32.f16.f16.f32 "
                        "{%0,%1,%2,%3}, {%4,%5,%6,%7}, {%8,%9}, {%0,%1,%2,%3};"
                        : "+f"(acc[mf][nf][0]), "+f"(acc[mf][nf][1]),
                          "+f"(acc[mf][nf][2]), "+f"(acc[mf][nf][3])
                        : "r"(a[mf][0]), "r"(a[mf][1]), "r"(a[mf][2]), "r"(a[mf][3]),
                          "r"(b[nf][0]), "r"(b[nf][1]));
                }
        }
    }

    const int row0 = bm + wm * 64 + (lane >> 2);
    const int col0 = bn + wn * 32 + (lane & 3) * 2;
#pragma unroll
    for (int mf = 0; mf < 4; mf++)
#pragma unroll
        for (int nf = 0; nf < 4; nf++) {
            int r = row0 + mf * 16;
            int c = col0 + nf * 8;
            if (HALF_OUT) {
                __half* C = (__half*)Cv;
                *(__half2*)(C + (size_t)r * N + c)       = __floats2half2_rn(acc[mf][nf][0], acc[mf][nf][1]);
                *(__half2*)(C + (size_t)(r + 8) * N + c) = __floats2half2_rn(acc[mf][nf][2], acc[mf][nf][3]);
            } else {
                float* C = (float*)Cv;
                *(float2*)(C + (size_t)r * N + c)       = make_float2(acc[mf][nf][0], acc[mf][nf][1]);
                *(float2*)(C + (size_t)(r + 8) * N + c) = make_float2(acc[mf][nf][2], acc[mf][nf][3]);
            }
        }
}

__global__ __launch_bounds__(256) void qkvg_gemm16(const __half* __restrict__ xn16,
                                                   float* __restrict__ qo, float* __restrict__ ko,
                                                   float* __restrict__ vo, float* __restrict__ go) {
    extern __shared__ uint32_t su[];
    int nt = blockIdx.x;
    const __half* W; float* C; int N, bn;
    if (nt < 8)       { W = g_qw16; C = qo; N = HID; bn = nt << 7; }
    else if (nt < 16) { W = g_kw16; C = ko; N = HID; bn = (nt - 8) << 7; }
    else if (nt < 32) { W = g_vw16; C = vo; N = VAL; bn = (nt - 16) << 7; }
    else              { W = g_gw16; C = go; N = VAL; bn = (nt - 32) << 7; }
    gemm16_body<false>(xn16, W, C, N, HID, blockIdx.y * 128, bn, su);
}

__global__ __launch_bounds__(256) void gemm16_h(const __half* __restrict__ A,
                                                const __half* __restrict__ W,
                                                __half* __restrict__ C, int N, int K) {
    extern __shared__ uint32_t su[];
    gemm16_body<true>(A, W, C, N, K, blockIdx.y * 128, blockIdx.x * 128, su);
}
__global__ __launch_bounds__(256) void gemm16_f(const __half* __restrict__ A,
                                                const __half* __restrict__ W,
                                                float* __restrict__ C, int N, int K) {
    extern __shared__ uint32_t su[];
    gemm16_body<false>(A, W, C, N, K, blockIdx.y * 128, blockIdx.x * 128, su);
}

// ---------------- a/b thin projections + gate scalars (8 rows/block, weight reuse) ----------------
__global__ __launch_bounds__(256) void proj_ab_kernel(const float* __restrict__ X,
                               const float* __restrict__ a_w, const float* __restrict__ b_w,
                               const float* __restrict__ dt_bias, const float* __restrict__ A_log,
                               float* __restrict__ beta, float* __restrict__ eg) {
    __shared__ float sx[8][HID];
    const int t0 = blockIdx.x * 8;
    const int tid = threadIdx.x;
#pragma unroll
    for (int r = 0; r < 8; r++)
        ((float4*)sx[r])[tid] = ((const float4*)(X + (size_t)(t0 + r) * HID))[tid];
    __syncthreads();
    const int warp = tid >> 5, lane = tid & 31;
#pragma unroll
    for (int pass = 0; pass < 2; pass++) {
        int h = warp + pass * 8;
        const float4* ar = (const float4*)(a_w + (size_t)h * HID);
        const float4* br = (const float4*)(b_w + (size_t)h * HID);
        float sa[8], sb[8];
#pragma unroll
        for (int r = 0; r < 8; r++) { sa[r] = 0.f; sb[r] = 0.f; }
#pragma unroll
        for (int i = 0; i < 8; i++) {
            float4 a4 = ar[lane + i * 32];
            float4 b4 = br[lane + i * 32];
#pragma unroll
            for (int r = 0; r < 8; r++) {
                float4 x4 = ((const float4*)sx[r])[lane + i * 32];
                sa[r] = fmaf(x4.x, a4.x, fmaf(x4.y, a4.y, fmaf(x4.z, a4.z, fmaf(x4.w, a4.w, sa[r]))));
                sb[r] = fmaf(x4.x, b4.x, fmaf(x4.y, b4.y, fmaf(x4.z, b4.z, fmaf(x4.w, b4.w, sb[r]))));
            }
        }
#pragma unroll
        for (int r = 0; r < 8; r++) {
            for (int o = 16; o > 0; o >>= 1) {
                sa[r] += __shfl_xor_sync(~0u, sa[r], o);
                sb[r] += __shfl_xor_sync(~0u, sb[r], o);
            }
        }
        if (lane == 0) {
            float Ae = expf(A_log[h]);
            float db = dt_bias[h];
#pragma unroll
            for (int r = 0; r < 8; r++) {
                beta[(size_t)(t0 + r) * NH + h] = 1.f / (1.f + expf(-sb[r]));
                float xv = sa[r] + db;
                float sp = (xv > 20.f) ? xv : log1pf(expf(xv));
                eg[(size_t)(t0 + r) * NH + h] = expf(-Ae * sp);
            }
        }
    }
}

// ---------------- conv(K=4)+silu + per-head postproc for q and k ----------------
__global__ void conv_qk2_kernel(const float* __restrict__ qpre, const float* __restrict__ kpre,
                                const float* __restrict__ cwq, const float* __restrict__ cwk,
                                float* __restrict__ qout, float* __restrict__ kout) {
    const int kmode = blockIdx.y;
    const float* pre = kmode ? kpre : qpre;
    const float* cw  = kmode ? cwk : cwq;
    float* out       = kmode ? kout : qout;
    int gw = blockIdx.x * 4 + (threadIdx.x >> 5);
    int lane = threadIdx.x & 31;
    int t = gw >> 4, h = gw & 15;
    float y[2];
#pragma unroll
    for (int e = 0; e < 2; e++) {
        int d = lane + e * 32;
        int c = h * DK + d;
        float acc = 0.f;
#pragma unroll
        for (int i = 0; i < CONV; i++) {
            int tt = t - (CONV - 1) + i;
            float xv = (tt >= 0) ? pre[(size_t)tt * HID + c] : 0.f;
            acc += xv * cw[c * CONV + i];
        }
        y[e] = acc / (1.f + expf(-acc));
    }
    if (kmode) {
        float m = y[0] + y[1];
        for (int o = 16; o > 0; o >>= 1) m += __shfl_xor_sync(~0u, m, o);
        m *= (1.f / DK);
        y[0] -= m; y[1] -= m;
    }
    float ss = y[0] * y[0] + y[1] * y[1];
    for (int o = 16; o > 0; o >>= 1) ss += __shfl_xor_sync(~0u, ss, o);
    float sc = rsqrtf(ss + 1e-6f);
    if (!kmode) sc *= 0.125f;
#pragma unroll
    for (int e = 0; e < 2; e++) {
        int d = lane + e * 32;
        out[(size_t)t * HID + h * DK + d] = y[e] * sc;
    }
}

// ---------------- conv(K=4)+silu for v (float4: 4 channels/thread) ----------------
__global__ void conv_v_kernel(const float* __restrict__ pre, const float* __restrict__ cw,
                              float* __restrict__ out) {
    int i = blockIdx.x * blockDim.x + threadIdx.x;   // float4 index
    if (i >= TT * VAL / 4) return;
    int t  = i >> 9;
    int c4 = i & (VAL / 4 - 1);
    float4 ws[4];
#pragma unroll
    for (int u = 0; u < 4; u++) ws[u] = ((const float4*)cw)[c4 * 4 + u];
    const float* wsf = (const float*)ws;
    float accf[4] = {0.f, 0.f, 0.f, 0.f};
#pragma unroll
    for (int j = 0; j < CONV; j++) {
        int tt = t - (CONV - 1) + j;
        if (tt >= 0) {
            float4 xv = ((const float4*)pre)[tt * (VAL / 4) + c4];
            const float* xf = (const float*)&xv;
#pragma unroll
            for (int u = 0; u < 4; u++)
                accf[u] = fmaf(xf[u], wsf[u * 4 + j], accf[u]);
        }
    }
    float4 o;
    o.x = accf[0] / (1.f + expf(-accf[0]));
    o.y = accf[1] / (1.f + expf(-accf[1]));
    o.z = accf[2] / (1.f + expf(-accf[2]));
    o.w = accf[3] / (1.f + expf(-accf[3]));
    ((float4*)out)[i] = o;
}

// ---------------- gated delta-rule scan (shfl butterfly, tree dot) ----------------
#define SK_OFF   0
#define SQ_OFF   8192
#define SV_OFF   16384
#define SBE_OFF  18432
#define SCAN_SMEM_F (SBE_OFF + 256)
__global__ __launch_bounds__(128) void scan_kernel(const float* __restrict__ q,
                                                   const float* __restrict__ k,
                                                   const float* __restrict__ v,
                                                   const float* __restrict__ beta,
                                                   const float* __restrict__ eg,
                                                   float* __restrict__ o) {
    extern __shared__ float ss[];
    const int h   = blockIdx.x >> 3;
    const int cg  = blockIdx.x & 7;
    const int tid = threadIdx.x;
    const int colL = tid >> 3;
    const int sub  = tid & 7;
    const int col  = cg * 16 + colL;

    float s[8];
#pragma unroll
    for (int i = 0; i < 8; i++) s[i] = 0.f;

    auto load_chunk = [&](int c0, int buf) {
#pragma unroll
        for (int i = 0; i < 8; i++) {
            int idx = tid + i * 128;
            int tl = idx >> 4, f4 = idx & 15;
            CP_ASYNC16(smaddr(&ss[SK_OFF + buf * 4096 + tl * 64 + f4 * 4]),
                       k + (size_t)(c0 + tl) * HID + h * DK + f4 * 4);
            CP_ASYNC16(smaddr(&ss[SQ_OFF + buf * 4096 + tl * 64 + f4 * 4]),
                       q + (size_t)(c0 + tl) * HID + h * DK + f4 * 4);
        }
#pragma unroll
        for (int i = 0; i < 2; i++) {
            int idx = tid + i * 128;
            int tl = idx >> 2, f4 = idx & 3;
            CP_ASYNC16(smaddr(&ss[SV_OFF + buf * 1024 + tl * 16 + f4 * 4]),
                       v + (size_t)(c0 + tl) * VAL + h * DV + cg * 16 + f4 * 4);
        }
        if (tid < 64)
            CP_ASYNC4(smaddr(&ss[SBE_OFF + buf * 128 + tid]),
                      beta + (size_t)(c0 + tid) * NH + h);
        else
            CP_ASYNC4(smaddr(&ss[SBE_OFF + buf * 128 + tid]),
                      eg + (size_t)(c0 + tid - 64) * NH + h);
    };

    load_chunk(0, 0); CP_COMMIT();

    for (int ch = 0; ch < TT / 64; ch++) {
        const int buf = ch & 1;
        if (ch + 1 < TT / 64) { load_chunk((ch + 1) * 64, buf ^ 1); CP_COMMIT(); CP_WAIT1(); }
        else CP_WAIT0();
        __syncthreads();

        const float* skb = &ss[SK_OFF + buf * 4096];
        const float* sqb = &ss[SQ_OFF + buf * 4096];
        const float* svb = &ss[SV_OFF + buf * 1024];
        const float* sbb = &ss[SBE_OFF + buf * 128];
        const int c0 = ch * 64;

#pragma unroll 2
        for (int tl = 0; tl < 64; tl++) {
            float bt  = sbb[tl];
            float egv = sbb[64 + tl];
            float vt  = svb[tl * 16 + colL];
            float4 k0 = *(const float4*)&skb[tl * 64 + sub * 8];
            float4 k1 = *(const float4*)&skb[tl * 64 + sub * 8 + 4];

            // dot(k, s) as pair-product tree (chain: mul + 3 adds), decay applied after
            float m0 = k0.x * s[0], m1 = k0.y * s[1], m2 = k0.z * s[2], m3 = k0.w * s[3];
            float m4 = k1.x * s[4], m5 = k1.y * s[5], m6 = k1.z * s[6], m7 = k1.w * s[7];
            float d0 = (m0 + m1) + (m2 + m3);
            float d1 = (m4 + m5) + (m6 + m7);
            float kv = (d0 + d1) * egv;
            kv += __shfl_xor_sync(~0u, kv, 1);
            kv += __shfl_xor_sync(~0u, kv, 2);
            kv += __shfl_xor_sync(~0u, kv, 4);

            // decay multiplies run in parallel with the dot/shfl chain
            float p0 = s[0] * egv, p1 = s[1] * egv, p2 = s[2] * egv, p3 = s[3] * egv;
            float p4 = s[4] * egv, p5 = s[5] * egv, p6 = s[6] * egv, p7 = s[7] * egv;

            float vn = (vt - kv) * bt;

            s[0] = fmaf(k0.x, vn, p0); s[1] = fmaf(k0.y, vn, p1);
            s[2] = fmaf(k0.z, vn, p2); s[3] = fmaf(k0.w, vn, p3);
            s[4] = fmaf(k1.x, vn, p4); s[5] = fmaf(k1.y, vn, p5);
            s[6] = fmaf(k1.z, vn, p6); s[7] = fmaf(k1.w, vn, p7);

            float4 q0 = *(const float4*)&sqb[tl * 64 + sub * 8];
            float4 q1 = *(const float4*)&sqb[tl * 64 + sub * 8 + 4];
            float oa  = fmaf(q0.w, s[3], fmaf(q0.z, s[2], fmaf(q0.y, s[1], q0.x * s[0])));
            float ob2 = fmaf(q1.w, s[7], fmaf(q1.z, s[6], fmaf(q1.y, s[5], q1.x * s[4])));
            float ov = oa + ob2;
            ov += __shfl_xor_sync(~0u, ov, 1);
            ov += __shfl_xor_sync(~0u, ov, 2);
            ov += __shfl_xor_sync(~0u, ov, 4);
            if (sub == 0) o[(size_t)(c0 + tl) * VAL + h * DV + col] = ov;
        }
        __syncthreads();
    }
}

// ---------------- gated RMSNorm on heads + silu(gate) -> f16 ----------------
__global__ void gated_norm_kernel(const float* __restrict__ o, const float* __restrict__ gate,
                                  const float* __restrict__ onw, __half* __restrict__ og16) {
    int gw = blockIdx.x * 4 + (threadIdx.x >> 5);
    int lane = threadIdx.x & 31;
    int t = gw >> 4, h = gw & 15;
    const float* orow = o + (size_t)t * VAL + h * DV;
    float4 vv = ((const float4*)orow)[lane];
    float ssum = vv.x * vv.x + vv.y * vv.y + vv.z * vv.z + vv.w * vv.w;
    for (int off = 16; off > 0; off >>= 1) ssum += __shfl_xor_sync(~0u, ssum, off);
    float sc = rsqrtf(ssum * (1.f / DV) + 1e-5f);
    float4 gt = ((const float4*)(gate + (size_t)t * VAL + h * DV))[lane];
    float4 wn = ((const float4*)onw)[lane];
    float o0 = vv.x * sc * wn.x * (gt.x / (1.f + expf(-gt.x)));
    float o1 = vv.y * sc * wn.y * (gt.y / (1.f + expf(-gt.y)));
    float o2 = vv.z * sc * wn.z * (gt.z / (1.f + expf(-gt.z)));
    float o3 = vv.w * sc * wn.w * (gt.w / (1.f + expf(-gt.w)));
    __half2* og2 = (__half2*)(og16 + (size_t)t * VAL + h * DV);
    og2[lane * 2]     = __floats2half2_rn(o0, o1);
    og2[lane * 2 + 1] = __floats2half2_rn(o2, o3);
}

// ---------------- launch ----------------
extern "C" void kernel_launch(void* const* d_in, const int* in_sizes, int n_in,
                              void* d_out, int out_size) {
    const float* hs       = (const float*)d_in[0];
    const float* norm_w   = (const float*)d_in[1];
    const float* q_w      = (const float*)d_in[2];
    const float* k_w      = (const float*)d_in[3];
    const float* v_w      = (const float*)d_in[4];
    const float* a_w      = (const float*)d_in[5];
    const float* b_w      = (const float*)d_in[6];
    const float* g_w      = (const float*)d_in[7];
    const float* dt_bias  = (const float*)d_in[8];
    const float* A_log    = (const float*)d_in[9];
    const float* conv_q_w = (const float*)d_in[10];
    const float* conv_k_w = (const float*)d_in[11];
    const float* conv_v_w = (const float*)d_in[12];
    const float* o_norm_w = (const float*)d_in[13];
    const float* o_proj_w = (const float*)d_in[14];
    const float* out_proj_w = (const float*)d_in[15];
    float* out = (float*)d_out;

    float *xn, *qpre, *kpre, *vpre, *gate, *qb, *kb, *vb, *beta, *eg, *ob;
    __half *xn16, *og16, *t116, *opw16, *ow16;
    cudaGetSymbolAddress((void**)&xn,   g_xn);
    cudaGetSymbolAddress((void**)&qpre, g_qpre);
    cudaGetSymbolAddress((void**)&kpre, g_kpre);
    cudaGetSymbolAddress((void**)&vpre, g_vpre);
    cudaGetSymbolAddress((void**)&gate, g_gate);
    cudaGetSymbolAddress((void**)&qb,   g_q);
    cudaGetSymbolAddress((void**)&kb,   g_k);
    cudaGetSymbolAddress((void**)&vb,   g_v);
    cudaGetSymbolAddress((void**)&beta, g_beta);
    cudaGetSymbolAddress((void**)&eg,   g_eg);
    cudaGetSymbolAddress((void**)&ob,   g_o);
    cudaGetSymbolAddress((void**)&xn16, g_xn16);
    cudaGetSymbolAddress((void**)&og16, g_og16);
    cudaGetSymbolAddress((void**)&t116, g_t116);
    cudaGetSymbolAddress((void**)&opw16, g_opw16);
    cudaGetSymbolAddress((void**)&ow16,  g_ow16);

    static bool attr_set = false;
    if (!attr_set) {
        cudaFuncSetAttribute(qkvg_gemm16, cudaFuncAttributeMaxDynamicSharedMemorySize, GEMM16_SMEM_BYTES);
        cudaFuncSetAttribute(gemm16_h,    cudaFuncAttributeMaxDynamicSharedMemorySize, GEMM16_SMEM_BYTES);
        cudaFuncSetAttribute(gemm16_f,    cudaFuncAttributeMaxDynamicSharedMemorySize, GEMM16_SMEM_BYTES);
        cudaFuncSetAttribute(scan_kernel, cudaFuncAttributeMaxDynamicSharedMemorySize, SCAN_SMEM_F * 4);
        attr_set = true;
    }

    convert_w_kernel<<<(CW_TOTAL4 + 255) / 256, 256>>>(q_w, k_w, v_w, g_w, o_proj_w, out_proj_w);
    rmsnorm_kernel<<<TT, 256>>>(hs, norm_w, xn, xn16);

    qkvg_gemm16<<<dim3(48, TT / 128), 256, GEMM16_SMEM_BYTES>>>(xn16, qpre, kpre, vpre, gate);
    proj_ab_kernel<<<TT / 8, 256>>>(xn, a_w, b_w, dt_bias, A_log, beta, eg);

    conv_qk2_kernel<<<dim3((TT * NH) / 4, 2), 128>>>(qpre, kpre, conv_q_w, conv_k_w, qb, kb);
    conv_v_kernel<<<(TT * VAL / 4) / 256, 256>>>(vpre, conv_v_w, vb);

    scan_kernel<<<128, 128, SCAN_SMEM_F * 4>>>(qb, kb, vb, beta, eg, ob);

    gated_norm_kernel<<<(TT * NH) / 4, 128>>>(ob, gate, o_norm_w, og16);

    gemm16_h<<<dim3(HID / 128, TT / 128), 256, GEMM16_SMEM_BYTES>>>(og16, opw16, t116, HID, VAL);
    gemm16_f<<<dim3(HID / 128, TT / 128), 256, GEMM16_SMEM_BYTES>>>(t116, ow16, out, HID, HID);
}

// round 16
// speedup vs baseline: 2.9498x; 1.0031x over previous
#include <cuda_runtime.h>
#include <cuda_fp16.h>
#include <math.h>
#include <stdint.h>

// ---------------- problem constants ----------------
#define TT   2048
#define HID  1024
#define NH   16
#define DK   64
#define DV   128
#define VAL  2048   // NH*DV
#define CONV 4

// ---------------- scratch ----------------
__device__ __align__(16) float  g_xn  [TT * HID];
__device__ __align__(16) float  g_qpre[TT * HID];
__device__ __align__(16) float  g_kpre[TT * HID];
__device__ __align__(16) float  g_vpre[TT * VAL];
__device__ __align__(16) float  g_gate[TT * VAL];
__device__ __align__(16) float  g_q   [TT * HID];
__device__ __align__(16) float  g_k   [TT * HID];
__device__ __align__(16) float  g_v   [TT * VAL];
__device__ __align__(16) float  g_beta[TT * NH];
__device__ __align__(16) float  g_eg  [TT * NH];
__device__ __align__(16) float  g_o   [TT * VAL];

// fp16 operands
__device__ __align__(16) __half g_xn16 [TT * HID];
__device__ __align__(16) __half g_og16 [TT * VAL];
__device__ __align__(16) __half g_t116 [TT * HID];
__device__ __align__(16) __half g_qw16 [HID * HID];
__device__ __align__(16) __half g_kw16 [HID * HID];
__device__ __align__(16) __half g_vw16 [VAL * HID];
__device__ __align__(16) __half g_gw16 [VAL * HID];
__device__ __align__(16) __half g_opw16[HID * VAL];
__device__ __align__(16) __half g_ow16 [HID * HID];

// ---------------- helpers ----------------
__device__ __forceinline__ uint32_t smaddr(const void* p) {
    return (uint32_t)__cvta_generic_to_shared(p);
}
#define CP_ASYNC16(dst, src) \
    asm volatile("cp.async.cg.shared.global [%0], [%1], 16;" :: "r"(dst), "l"(src))
#define CP_ASYNC4(dst, src) \
    asm volatile("cp.async.ca.shared.global [%0], [%1], 4;" :: "r"(dst), "l"(src))
#define CP_COMMIT() asm volatile("cp.async.commit_group;")
#define CP_WAIT2()  asm volatile("cp.async.wait_group 2;")
#define CP_WAIT1()  asm volatile("cp.async.wait_group 1;")
#define CP_WAIT0()  asm volatile("cp.async.wait_group 0;")

// ---------------- weight f32 -> f16 conversion ----------------
#define CW_TOTAL4 2359296
__global__ void convert_w_kernel(const float* __restrict__ qw, const float* __restrict__ kw,
                                 const float* __restrict__ vw, const float* __restrict__ gw,
                                 const float* __restrict__ opw, const float* __restrict__ ow) {
    int gid = blockIdx.x * 256 + threadIdx.x;
    if (gid >= CW_TOTAL4) return;
    const float* s; __half* d; int o;
    if      (gid < 262144)  { s = qw;  d = g_qw16;  o = gid; }
    else if (gid < 524288)  { s = kw;  d = g_kw16;  o = gid - 262144; }
    else if (gid < 1048576) { s = vw;  d = g_vw16;  o = gid - 524288; }
    else if (gid < 1572864) { s = gw;  d = g_gw16;  o = gid - 1048576; }
    else if (gid < 2097152) { s = opw; d = g_opw16; o = gid - 1572864; }
    else                    { s = ow;  d = g_ow16;  o = gid - 2097152; }
    float4 v = ((const float4*)s)[o];
    ((__half2*)d)[o * 2]     = __floats2half2_rn(v.x, v.y);
    ((__half2*)d)[o * 2 + 1] = __floats2half2_rn(v.z, v.w);
}

// ---------------- RMSNorm (writes f32 + f16) ----------------
__global__ void rmsnorm_kernel(const float* __restrict__ x, const float* __restrict__ w,
                               float* __restrict__ y, __half* __restrict__ y16) {
    int row = blockIdx.x;
    int tid = threadIdx.x;
    float4 v = ((const float4*)(x + (size_t)row * HID))[tid];
    float s = v.x * v.x + v.y * v.y + v.z * v.z + v.w * v.w;
    __shared__ float red[256];
    red[tid] = s; __syncthreads();
    for (int o = 128; o > 0; o >>= 1) { if (tid < o) red[tid] += red[tid + o]; __syncthreads(); }
    float scale = rsqrtf(red[0] * (1.f / HID) + 1e-6f);
    float4 wv = ((const float4*)w)[tid];
    float4 out;
    out.x = v.x * scale * wv.x; out.y = v.y * scale * wv.y;
    out.z = v.z * scale * wv.z; out.w = v.w * scale * wv.w;
    ((float4*)(y + (size_t)row * HID))[tid] = out;
    __half2* y2 = (__half2*)(y16 + (size_t)row * HID);
    y2[tid * 2]     = __floats2half2_rn(out.x, out.y);
    y2[tid * 2 + 1] = __floats2half2_rn(out.z, out.w);
}

// ---------------- fp16 tensor-core GEMM body ----------------
#define STAGE_U32 4096
#define GEMM16_SMEM_BYTES (4 * STAGE_U32 * 4)

template<bool HALF_OUT>
__device__ __forceinline__ void gemm16_body(const __half* __restrict__ A,
                                            const __half* __restrict__ W,
                                            void* __restrict__ Cv,
                                            int N, int K, int bm, int bn,
                                            uint32_t* su) {
    const int tid  = threadIdx.x;
    const int lane = tid & 31;
    const int warp = tid >> 5;
    const int wm   = warp & 1;
    const int wn   = warp >> 1;

    float acc[4][4][4];
#pragma unroll
    for (int i = 0; i < 4; i++)
#pragma unroll
        for (int j = 0; j < 4; j++)
#pragma unroll
            for (int r = 0; r < 4; r++) acc[i][j][r] = 0.f;

    uint32_t sbase = smaddr(su);
    int m_[2], q_[2];
#pragma unroll
    for (int p = 0; p < 2; p++) { int idx = tid + p * 256; m_[p] = idx >> 2; q_[p] = idx & 3; }

    auto load_tile = [&](int t, int stage) {
        uint32_t sb = sbase + (uint32_t)stage * STAGE_U32 * 4;
#pragma unroll
        for (int p = 0; p < 2; p++) {
            int m = m_[p], q = q_[p];
            int mf = m >> 4, mr = m & 15, ks = q >> 1;
            int regA = (mr >> 3) + ((q & 1) << 1);
            uint32_t dA = sb + (uint32_t)((((mf * 2 + ks) * 4 + regA) * 32 + (mr & 7) * 4)) * 4u;
            CP_ASYNC16(dA, A + (size_t)(bm + m) * K + t * 32 + q * 8);
            int nf = m >> 3, nr = m & 7;
            int regB = q & 1;
            uint32_t dB = sb + (uint32_t)(2048 + (((nf * 2 + ks) * 2 + regB) * 32 + nr * 4)) * 4u;
            CP_ASYNC16(dB, W + (size_t)(bn + m) * K + t * 32 + q * 8);
        }
    };

    const int NT = K >> 5;
    load_tile(0, 0); CP_COMMIT();
    load_tile(1, 1); CP_COMMIT();
    load_tile(2, 2); CP_COMMIT();

    for (int t = 0; t < NT; t++) {
        CP_WAIT2();
        __syncthreads();
        if (t + 3 < NT) load_tile(t + 3, (t + 3) & 3);
        CP_COMMIT();

        const uint32_t* Ab = su + (t & 3) * STAGE_U32;
        const uint32_t* Bb = Ab + 2048;
#pragma unroll
        for (int ks = 0; ks < 2; ks++) {
            uint32_t a[4][4], b[4][2];
#pragma unroll
            for (int mf = 0; mf < 4; mf++) {
                int base = (((wm * 4 + mf) * 2 + ks) * 4) * 32 + lane;
#pragma unroll
                for (int r = 0; r < 4; r++) a[mf][r] = Ab[base + r * 32];
            }
#pragma unroll
            for (int nf = 0; nf < 4; nf++) {
                int base = (((wn * 4 + nf) * 2 + ks) * 2) * 32 + lane;
#pragma unroll
                for (int r = 0; r < 2; r++) b[nf][r] = Bb[base + r * 32];
            }
#pragma unroll
            for (int mf = 0; mf < 4; mf++)
#pragma unroll
                for (int nf = 0; nf < 4; nf++) {
                    asm volatile(
                        "mma.sync.aligned.m16n8k16.row.col.f32.f16.f16.f32 "
                        "{%0,%1,%2,%3}, {%4,%5,%6,%7}, {%8,%9}, {%0,%1,%2,%3};"
                        : "+f"(acc[mf][nf][0]), "+f"(acc[mf][nf][1]),
                          "+f"(acc[mf][nf][2]), "+f"(acc[mf][nf][3])
                        : "r"(a[mf][0]), "r"(a[mf][1]), "r"(a[mf][2]), "r"(a[mf][3]),
                          "r"(b[nf][0]), "r"(b[nf][1]));
                }
        }
    }

    const int row0 = bm + wm * 64 + (lane >> 2);
    const int col0 = bn + wn * 32 + (lane & 3) * 2;
#pragma unroll
    for (int mf = 0; mf < 4; mf++)
#pragma unroll
        for (int nf = 0; nf < 4; nf++) {
            int r = row0 + mf * 16;
            int c = col0 + nf * 8;
            if (HALF_OUT) {
                __half* C = (__half*)Cv;
                *(__half2*)(C + (size_t)r * N + c)       = __floats2half2_rn(acc[mf][nf][0], acc[mf][nf][1]);
                *(__half2*)(C + (size_t)(r + 8) * N + c) = __floats2half2_rn(acc[mf][nf][2], acc[mf][nf][3]);
            } else {
                float* C = (float*)Cv;
                *(float2*)(C + (size_t)r * N + c)       = make_float2(acc[mf][nf][0], acc[mf][nf][1]);
                *(float2*)(C + (size_t)(r + 8) * N + c) = make_float2(acc[mf][nf][2], acc[mf][nf][3]);
            }
        }
}

__global__ __launch_bounds__(256) void qkvg_gemm16(const __half* __restrict__ xn16,
                                                   float* __restrict__ qo, float* __restrict__ ko,
                                                   float* __restrict__ vo, float* __restrict__ go) {
    extern __shared__ uint32_t su[];
    int nt = blockIdx.x;
    const __half* W; float* C; int N, bn;
    if (nt < 8)       { W = g_qw16; C = qo; N = HID; bn = nt << 7; }
    else if (nt < 16) { W = g_kw16; C = ko; N = HID; bn = (nt - 8) << 7; }
    else if (nt < 32) { W = g_vw16; C = vo; N = VAL; bn = (nt - 16) << 7; }
    else              { W = g_gw16; C = go; N = VAL; bn = (nt - 32) << 7; }
    gemm16_body<false>(xn16, W, C, N, HID, blockIdx.y * 128, bn, su);
}

__global__ __launch_bounds__(256) void gemm16_h(const __half* __restrict__ A,
                                                const __half* __restrict__ W,
                                                __half* __restrict__ C, int N, int K) {
    extern __shared__ uint32_t su[];
    gemm16_body<true>(A, W, C, N, K, blockIdx.y * 128, blockIdx.x * 128, su);
}
__global__ __launch_bounds__(256) void gemm16_f(const __half* __restrict__ A,
                                                const __half* __restrict__ W,
                                                float* __restrict__ C, int N, int K) {
    extern __shared__ uint32_t su[];
    gemm16_body<false>(A, W, C, N, K, blockIdx.y * 128, blockIdx.x * 128, su);
}

// ---------------- a/b thin projections + gate scalars (8 rows/block, weight reuse) ----------------
__global__ __launch_bounds__(256) void proj_ab_kernel(const float* __restrict__ X,
                               const float* __restrict__ a_w, const float* __restrict__ b_w,
                               const float* __restrict__ dt_bias, const float* __restrict__ A_log,
                               float* __restrict__ beta, float* __restrict__ eg) {
    __shared__ float sx[8][HID];
    const int t0 = blockIdx.x * 8;
    const int tid = threadIdx.x;
#pragma unroll
    for (int r = 0; r < 8; r++)
        ((float4*)sx[r])[tid] = ((const float4*)(X + (size_t)(t0 + r) * HID))[tid];
    __syncthreads();
    const int warp = tid >> 5, lane = tid & 31;
#pragma unroll
    for (int pass = 0; pass < 2; pass++) {
        int h = warp + pass * 8;
        const float4* ar = (const float4*)(a_w + (size_t)h * HID);
        const float4* br = (const float4*)(b_w + (size_t)h * HID);
        float sa[8], sb[8];
#pragma unroll
        for (int r = 0; r < 8; r++) { sa[r] = 0.f; sb[r] = 0.f; }
#pragma unroll
        for (int i = 0; i < 8; i++) {
            float4 a4 = ar[lane + i * 32];
            float4 b4 = br[lane + i * 32];
#pragma unroll
            for (int r = 0; r < 8; r++) {
                float4 x4 = ((const float4*)sx[r])[lane + i * 32];
                sa[r] = fmaf(x4.x, a4.x, fmaf(x4.y, a4.y, fmaf(x4.z, a4.z, fmaf(x4.w, a4.w, sa[r]))));
                sb[r] = fmaf(x4.x, b4.x, fmaf(x4.y, b4.y, fmaf(x4.z, b4.z, fmaf(x4.w, b4.w, sb[r]))));
            }
        }
#pragma unroll
        for (int r = 0; r < 8; r++) {
            for (int o = 16; o > 0; o >>= 1) {
                sa[r] += __shfl_xor_sync(~0u, sa[r], o);
                sb[r] += __shfl_xor_sync(~0u, sb[r], o);
            }
        }
        if (lane == 0) {
            float Ae = expf(A_log[h]);
            float db = dt_bias[h];
#pragma unroll
            for (int r = 0; r < 8; r++) {
                beta[(size_t)(t0 + r) * NH + h] = 1.f / (1.f + expf(-sb[r]));
                float xv = sa[r] + db;
                float sp = (xv > 20.f) ? xv : log1pf(expf(xv));
                eg[(size_t)(t0 + r) * NH + h] = expf(-Ae * sp);
            }
        }
    }
}

// ---------------- conv(K=4)+silu + per-head postproc for q and k ----------------
__global__ void conv_qk2_kernel(const float* __restrict__ qpre, const float* __restrict__ kpre,
                                const float* __restrict__ cwq, const float* __restrict__ cwk,
                                float* __restrict__ qout, float* __restrict__ kout) {
    const int kmode = blockIdx.y;
    const float* pre = kmode ? kpre : qpre;
    const float* cw  = kmode ? cwk : cwq;
    float* out       = kmode ? kout : qout;
    int gw = blockIdx.x * 4 + (threadIdx.x >> 5);
    int lane = threadIdx.x & 31;
    int t = gw >> 4, h = gw & 15;
    float y[2];
#pragma unroll
    for (int e = 0; e < 2; e++) {
        int d = lane + e * 32;
        int c = h * DK + d;
        float acc = 0.f;
#pragma unroll
        for (int i = 0; i < CONV; i++) {
            int tt = t - (CONV - 1) + i;
            float xv = (tt >= 0) ? pre[(size_t)tt * HID + c] : 0.f;
            acc += xv * cw[c * CONV + i];
        }
        y[e] = acc / (1.f + expf(-acc));
    }
    if (kmode) {
        float m = y[0] + y[1];
        for (int o = 16; o > 0; o >>= 1) m += __shfl_xor_sync(~0u, m, o);
        m *= (1.f / DK);
        y[0] -= m; y[1] -= m;
    }
    float ss = y[0] * y[0] + y[1] * y[1];
    for (int o = 16; o > 0; o >>= 1) ss += __shfl_xor_sync(~0u, ss, o);
    float sc = rsqrtf(ss + 1e-6f);
    if (!kmode) sc *= 0.125f;
#pragma unroll
    for (int e = 0; e < 2; e++) {
        int d = lane + e * 32;
        out[(size_t)t * HID + h * DK + d] = y[e] * sc;
    }
}

// ---------------- conv(K=4)+silu for v (float4: 4 channels/thread) ----------------
__global__ void conv_v_kernel(const float* __restrict__ pre, const float* __restrict__ cw,
                              float* __restrict__ out) {
    int i = blockIdx.x * blockDim.x + threadIdx.x;   // float4 index
    if (i >= TT * VAL / 4) return;
    int t  = i >> 9;
    int c4 = i & (VAL / 4 - 1);
    float4 ws[4];
#pragma unroll
    for (int u = 0; u < 4; u++) ws[u] = ((const float4*)cw)[c4 * 4 + u];
    const float* wsf = (const float*)ws;
    float accf[4] = {0.f, 0.f, 0.f, 0.f};
#pragma unroll
    for (int j = 0; j < CONV; j++) {
        int tt = t - (CONV - 1) + j;
        if (tt >= 0) {
            float4 xv = ((const float4*)pre)[tt * (VAL / 4) + c4];
            const float* xf = (const float*)&xv;
#pragma unroll
            for (int u = 0; u < 4; u++)
                accf[u] = fmaf(xf[u], wsf[u * 4 + j], accf[u]);
        }
    }
    float4 o;
    o.x = accf[0] / (1.f + expf(-accf[0]));
    o.y = accf[1] / (1.f + expf(-accf[1]));
    o.z = accf[2] / (1.f + expf(-accf[2]));
    o.w = accf[3] / (1.f + expf(-accf[3]));
    ((float4*)out)[i] = o;
}

// ---------------- gated delta-rule scan (shfl butterfly, tree dot) ----------------
#define SK_OFF   0
#define SQ_OFF   8192
#define SV_OFF   16384
#define SBE_OFF  18432
#define SCAN_SMEM_F (SBE_OFF + 256)
__global__ __launch_bounds__(128) void scan_kernel(const float* __restrict__ q,
                                                   const float* __restrict__ k,
                                                   const float* __restrict__ v,
                                                   const float* __restrict__ beta,
                                                   const float* __restrict__ eg,
                                                   float* __restrict__ o) {
    extern __shared__ float ss[];
    const int h   = blockIdx.x >> 3;
    const int cg  = blockIdx.x & 7;
    const int tid = threadIdx.x;
    const int colL = tid >> 3;
    const int sub  = tid & 7;
    const int col  = cg * 16 + colL;

    float s[8];
#pragma unroll
    for (int i = 0; i < 8; i++) s[i] = 0.f;

    auto load_chunk = [&](int c0, int buf) {
#pragma unroll
        for (int i = 0; i < 8; i++) {
            int idx = tid + i * 128;
            int tl = idx >> 4, f4 = idx & 15;
            CP_ASYNC16(smaddr(&ss[SK_OFF + buf * 4096 + tl * 64 + f4 * 4]),
                       k + (size_t)(c0 + tl) * HID + h * DK + f4 * 4);
            CP_ASYNC16(smaddr(&ss[SQ_OFF + buf * 4096 + tl * 64 + f4 * 4]),
                       q + (size_t)(c0 + tl) * HID + h * DK + f4 * 4);
        }
#pragma unroll
        for (int i = 0; i < 2; i++) {
            int idx = tid + i * 128;
            int tl = idx >> 2, f4 = idx & 3;
            CP_ASYNC16(smaddr(&ss[SV_OFF + buf * 1024 + tl * 16 + f4 * 4]),
                       v + (size_t)(c0 + tl) * VAL + h * DV + cg * 16 + f4 * 4);
        }
        if (tid < 64)
            CP_ASYNC4(smaddr(&ss[SBE_OFF + buf * 128 + tid]),
                      beta + (size_t)(c0 + tid) * NH + h);
        else
            CP_ASYNC4(smaddr(&ss[SBE_OFF + buf * 128 + tid]),
                      eg + (size_t)(c0 + tid - 64) * NH + h);
    };

    load_chunk(0, 0); CP_COMMIT();

    for (int ch = 0; ch < TT / 64; ch++) {
        const int buf = ch & 1;
        if (ch + 1 < TT / 64) { load_chunk((ch + 1) * 64, buf ^ 1); CP_COMMIT(); CP_WAIT1(); }
        else CP_WAIT0();
        __syncthreads();

        const float* skb = &ss[SK_OFF + buf * 4096];
        const float* sqb = &ss[SQ_OFF + buf * 4096];
        const float* svb = &ss[SV_OFF + buf * 1024];
        const float* sbb = &ss[SBE_OFF + buf * 128];
        const int c0 = ch * 64;

#pragma unroll 2
        for (int tl = 0; tl < 64; tl++) {
            float bt  = sbb[tl];
            float egv = sbb[64 + tl];
            float vt  = svb[tl * 16 + colL];
            float4 k0 = *(const float4*)&skb[tl * 64 + sub * 8];
            float4 k1 = *(const float4*)&skb[tl * 64 + sub * 8 + 4];

            // dot(k, s) as pair-product tree (chain: mul + 3 adds), decay applied after
            float m0 = k0.x * s[0], m1 = k0.y * s[1], m2 = k0.z * s[2], m3 = k0.w * s[3];
            float m4 = k1.x * s[4], m5 = k1.y * s[5], m6 = k1.z * s[6], m7 = k1.w * s[7];
            float d0 = (m0 + m1) + (m2 + m3);
            float d1 = (m4 + m5) + (m6 + m7);
            float kv = (d0 + d1) * egv;
            kv += __shfl_xor_sync(~0u, kv, 1);
            kv += __shfl_xor_sync(~0u, kv, 2);
            kv += __shfl_xor_sync(~0u, kv, 4);

            // decay multiplies run in parallel with the dot/shfl chain
            float p0 = s[0] * egv, p1 = s[1] * egv, p2 = s[2] * egv, p3 = s[3] * egv;
            float p4 = s[4] * egv, p5 = s[5] * egv, p6 = s[6] * egv, p7 = s[7] * egv;

            float vn = (vt - kv) * bt;

            s[0] = fmaf(k0.x, vn, p0); s[1] = fmaf(k0.y, vn, p1);
            s[2] = fmaf(k0.z, vn, p2); s[3] = fmaf(k0.w, vn, p3);
            s[4] = fmaf(k1.x, vn, p4); s[5] = fmaf(k1.y, vn, p5);
            s[6] = fmaf(k1.z, vn, p6); s[7] = fmaf(k1.w, vn, p7);

            float4 q0 = *(const float4*)&sqb[tl * 64 + sub * 8];
            float4 q1 = *(const float4*)&sqb[tl * 64 + sub * 8 + 4];
            float oa  = fmaf(q0.w, s[3], fmaf(q0.z, s[2], fmaf(q0.y, s[1], q0.x * s[0])));
            float ob2 = fmaf(q1.w, s[7], fmaf(q1.z, s[6], fmaf(q1.y, s[5], q1.x * s[4])));
            float ov = oa + ob2;
            ov += __shfl_xor_sync(~0u, ov, 1);
            ov += __shfl_xor_sync(~0u, ov, 2);
            ov += __shfl_xor_sync(~0u, ov, 4);
            if (sub == 0) o[(size_t)(c0 + tl) * VAL + h * DV + col] = ov;
        }
        __syncthreads();
    }
}

// ---------------- gated RMSNorm on heads + silu(gate) -> f16 ----------------
__global__ void gated_norm_kernel(const float* __restrict__ o, const float* __restrict__ gate,
                                  const float* __restrict__ onw, __half* __restrict__ og16) {
    int gw = blockIdx.x * 4 + (threadIdx.x >> 5);
    int lane = threadIdx.x & 31;
    int t = gw >> 4, h = gw & 15;
    const float* orow = o + (size_t)t * VAL + h * DV;
    float4 vv = ((const float4*)orow)[lane];
    float ssum = vv.x * vv.x + vv.y * vv.y + vv.z * vv.z + vv.w * vv.w;
    for (int off = 16; off > 0; off >>= 1) ssum += __shfl_xor_sync(~0u, ssum, off);
    float sc = rsqrtf(ssum * (1.f / DV) + 1e-5f);
    float4 gt = ((const float4*)(gate + (size_t)t * VAL + h * DV))[lane];
    float4 wn = ((const float4*)onw)[lane];
    float o0 = vv.x * sc * wn.x * (gt.x / (1.f + expf(-gt.x)));
    float o1 = vv.y * sc * wn.y * (gt.y / (1.f + expf(-gt.y)));
    float o2 = vv.z * sc * wn.z * (gt.z / (1.f + expf(-gt.z)));
    float o3 = vv.w * sc * wn.w * (gt.w / (1.f + expf(-gt.w)));
    __half2* og2 = (__half2*)(og16 + (size_t)t * VAL + h * DV);
    og2[lane * 2]     = __floats2half2_rn(o0, o1);
    og2[lane * 2 + 1] = __floats2half2_rn(o2, o3);
}

// ---------------- launch ----------------
extern "C" void kernel_launch(void* const* d_in, const int* in_sizes, int n_in,
                              void* d_out, int out_size) {
    const float* hs       = (const float*)d_in[0];
    const float* norm_w   = (const float*)d_in[1];
    const float* q_w      = (const float*)d_in[2];
    const float* k_w      = (const float*)d_in[3];
    const float* v_w      = (const float*)d_in[4];
    const float* a_w      = (const float*)d_in[5];
    const float* b_w      = (const float*)d_in[6];
    const float* g_w      = (const float*)d_in[7];
    const float* dt_bias  = (const float*)d_in[8];
    const float* A_log    = (const float*)d_in[9];
    const float* conv_q_w = (const float*)d_in[10];
    const float* conv_k_w = (const float*)d_in[11];
    const float* conv_v_w = (const float*)d_in[12];
    const float* o_norm_w = (const float*)d_in[13];
    const float* o_proj_w = (const float*)d_in[14];
    const float* out_proj_w = (const float*)d_in[15];
    float* out = (float*)d_out;

    float *xn, *qpre, *kpre, *vpre, *gate, *qb, *kb, *vb, *beta, *eg, *ob;
    __half *xn16, *og16, *t116, *opw16, *ow16;
    cudaGetSymbolAddress((void**)&xn,   g_xn);
    cudaGetSymbolAddress((void**)&qpre, g_qpre);
    cudaGetSymbolAddress((void**)&kpre, g_kpre);
    cudaGetSymbolAddress((void**)&vpre, g_vpre);
    cudaGetSymbolAddress((void**)&gate, g_gate);
    cudaGetSymbolAddress((void**)&qb,   g_q);
    cudaGetSymbolAddress((void**)&kb,   g_k);
    cudaGetSymbolAddress((void**)&vb,   g_v);
    cudaGetSymbolAddress((void**)&beta, g_beta);
    cudaGetSymbolAddress((void**)&eg,   g_eg);
    cudaGetSymbolAddress((void**)&ob,   g_o);
    cudaGetSymbolAddress((void**)&xn16, g_xn16);
    cudaGetSymbolAddress((void**)&og16, g_og16);
    cudaGetSymbolAddress((void**)&t116, g_t116);
    cudaGetSymbolAddress((void**)&opw16, g_opw16);
    cudaGetSymbolAddress((void**)&ow16,  g_ow16);

    static bool attr_set = false;
    if (!attr_set) {
        cudaFuncSetAttribute(qkvg_gemm16, cudaFuncAttributeMaxDynamicSharedMemorySize, GEMM16_SMEM_BYTES);
        cudaFuncSetAttribute(gemm16_h,    cudaFuncAttributeMaxDynamicSharedMemorySize, GEMM16_SMEM_BYTES);
        cudaFuncSetAttribute(gemm16_f,    cudaFuncAttributeMaxDynamicSharedMemorySize, GEMM16_SMEM_BYTES);
        cudaFuncSetAttribute(scan_kernel, cudaFuncAttributeMaxDynamicSharedMemorySize, SCAN_SMEM_F * 4);
        attr_set = true;
    }

    convert_w_kernel<<<(CW_TOTAL4 + 255) / 256, 256>>>(q_w, k_w, v_w, g_w, o_proj_w, out_proj_w);
    rmsnorm_kernel<<<TT, 256>>>(hs, norm_w, xn, xn16);

    qkvg_gemm16<<<dim3(48, TT / 128), 256, GEMM16_SMEM_BYTES>>>(xn16, qpre, kpre, vpre, gate);
    proj_ab_kernel<<<TT / 8, 256>>>(xn, a_w, b_w, dt_bias, A_log, beta, eg);

    conv_qk2_kernel<<<dim3((TT * NH) / 4, 2), 128>>>(qpre, kpre, conv_q_w, conv_k_w, qb, kb);
    conv_v_kernel<<<(TT * VAL / 4) / 256, 256>>>(vpre, conv_v_w, vb);

    scan_kernel<<<128, 128, SCAN_SMEM_F * 4>>>(qb, kb, vb, beta, eg, ob);

    gated_norm_kernel<<<(TT * NH) / 4, 128>>>(ob, gate, o_norm_w, og16);

    gemm16_h<<<dim3(HID / 128, TT / 128), 256, GEMM16_SMEM_BYTES>>>(og16, opw16, t116, HID, VAL);
    gemm16_f<<<dim3(HID / 128, TT / 128), 256, GEMM16_SMEM_BYTES>>>(t116, ow16, out, HID, HID);
}